// round 1
// baseline (speedup 1.0000x reference)
#include <cuda_runtime.h>
#include <math.h>

#define NB   1024   // batch
#define NN   32     // n (state dim)
#define HIDD 512    // hidden
#define DD   400    // d = m*tau
#define NC   800    // n_con
#define MMOD 8      // m (u_bar length)
#define ADMM_ITERS 40
#define NEWTON_ITERS 12

// ---------------- device scratch (no allocations allowed) ----------------
__device__ float g_alpha;

__device__ float dH1[NB * HIDD];
__device__ float dH2[NB * HIDD];
__device__ float dV [NB * DD];
__device__ float dBc[NB * NC];     // b = g + X0^T H0^T
__device__ float dK [DD * DD];
__device__ float dXa[DD * DD];
__device__ float dXb[DD * DD];
__device__ float dT [DD * DD];
__device__ float dFK[NC * DD];     // F @ Kinv
__device__ float dG [NC * NC];     // F Kinv F^T
__device__ float dCm[NB * NC];     // 2 V Kinv F^T
__device__ float dWa[NB * NC];
__device__ float dWb[NB * NC];
__device__ float dY [NB * NC];
__device__ float dU [NB * DD];     // 2 V Kinv

// ---------------- generic strided SGEMM with fused epilogues ----------------
// C[i*Crs + j*Ccs] = epi( sum_k A[i*Ars + k*Acs] * B[k*Brs + j*Bcs] )
// epi codes:
//  0: out = acc
//  1: out = relu(acc + e0[j])
//  2: out = tanh(acc + e0[j]) * e1[j % mod]
//  3: out = acc + e0[j]
//  4: out = min(acc, e0[i*Nd+j])
//  5: s = acc + e0[ij] + e1[ij]; yn = max(s - e2[ij], 0); o1[ij] = yn; out = s - 2*yn
//  6: out = 2*acc
//  7: out = acc + 2*(i==j)
//  8: out = 2*e0[ij] - acc
//  9: out = acc + e0[ij]
#define TM 64
#define TN 64
#define TK 16

__global__ void sgemm(const float* __restrict__ A, int Ars, int Acs,
                      const float* __restrict__ B, int Brs, int Bcs,
                      float* __restrict__ C, long Crs, long Ccs,
                      int Md, int Nd, int Kd,
                      int epi, const float* e0, const float* e1, const float* e2,
                      float* o1, int mod)
{
    __shared__ float As[TK][TM + 1];   // padded: conflict-free transposed stores
    __shared__ float Bs[TK][TN];       // float4-aligned reads

    const int tid = threadIdx.x;
    const int tx = tid & 15;           // 0..15 -> N micro
    const int ty = tid >> 4;           // 0..15 -> M micro
    const int i0 = blockIdx.y * TM;
    const int j0 = blockIdx.x * TN;

    float acc[4][4];
#pragma unroll
    for (int a = 0; a < 4; a++)
#pragma unroll
        for (int b = 0; b < 4; b++) acc[a][b] = 0.f;

    for (int k0 = 0; k0 < Kd; k0 += TK) {
        // load A tile (64 x 16): consecutive tids -> consecutive k (coalesced for Acs==1)
#pragma unroll
        for (int t = 0; t < 4; t++) {
            int idx = tid + t * 256;
            int m = idx >> 4;
            int k = idx & 15;
            int gi = i0 + m, gk = k0 + k;
            As[k][m] = (gi < Md && gk < Kd) ? A[(long)gi * Ars + (long)gk * Acs] : 0.f;
        }
        // load B tile (16 x 64): consecutive tids -> consecutive j (coalesced for Bcs==1)
#pragma unroll
        for (int t = 0; t < 4; t++) {
            int idx = tid + t * 256;
            int k = idx >> 6;
            int j = idx & 63;
            int gk = k0 + k, gj = j0 + j;
            Bs[k][j] = (gk < Kd && gj < Nd) ? B[(long)gk * Brs + (long)gj * Bcs] : 0.f;
        }
        __syncthreads();

#pragma unroll
        for (int k = 0; k < TK; k++) {
            float av[4], bv[4];
#pragma unroll
            for (int ii = 0; ii < 4; ii++) av[ii] = As[k][(ty << 2) + ii];
            float4 b4 = *reinterpret_cast<const float4*>(&Bs[k][tx << 2]);
            bv[0] = b4.x; bv[1] = b4.y; bv[2] = b4.z; bv[3] = b4.w;
#pragma unroll
            for (int ii = 0; ii < 4; ii++)
#pragma unroll
                for (int jj = 0; jj < 4; jj++)
                    acc[ii][jj] = fmaf(av[ii], bv[jj], acc[ii][jj]);
        }
        __syncthreads();
    }

#pragma unroll
    for (int ii = 0; ii < 4; ii++) {
        int i = i0 + (ty << 2) + ii;
        if (i >= Md) continue;
#pragma unroll
        for (int jj = 0; jj < 4; jj++) {
            int j = j0 + (tx << 2) + jj;
            if (j >= Nd) continue;
            float v = acc[ii][jj];
            long rm = (long)i * Nd + j;
            float out;
            switch (epi) {
                default:
                case 0: out = v; break;
                case 1: out = fmaxf(v + e0[j], 0.f); break;
                case 2: out = tanhf(v + e0[j]) * e1[j % mod]; break;
                case 3: out = v + e0[j]; break;
                case 4: out = fminf(v, e0[rm]); break;
                case 5: {
                    float s  = v + e0[rm] + e1[rm];
                    float yn = fmaxf(s - e2[rm], 0.f);
                    o1[rm] = yn;
                    out = s - 2.f * yn;
                } break;
                case 6: out = 2.f * v; break;
                case 7: out = (i == j) ? v + 2.f : v; break;
                case 8: out = 2.f * e0[rm] - v; break;
                case 9: out = v + e0[rm]; break;
            }
            C[(long)i * Crs + (long)j * Ccs] = out;
        }
    }
}

// ---------------- small helper kernels ----------------
__global__ void gershgorin_kernel(const float* __restrict__ K, int n)
{
    __shared__ float red[512];
    float mx = 0.f;
    for (int i = threadIdx.x; i < n; i += blockDim.x) {
        float s = 0.f;
        for (int j = 0; j < n; j++) s += fabsf(K[i * n + j]);
        mx = fmaxf(mx, s);
    }
    red[threadIdx.x] = mx;
    __syncthreads();
    for (int s = 256; s > 0; s >>= 1) {
        if (threadIdx.x < s) red[threadIdx.x] = fmaxf(red[threadIdx.x], red[threadIdx.x + s]);
        __syncthreads();
    }
    if (threadIdx.x == 0) g_alpha = 2.f / (2.f + red[0]);   // X0 = alpha*I, alpha=2/(lmin+gersh)
}

__global__ void init_diag_kernel(float* __restrict__ X, int n)
{
    int idx = blockIdx.x * blockDim.x + threadIdx.x;
    if (idx < n * n) {
        int i = idx / n, j = idx - i * n;
        X[idx] = (i == j) ? g_alpha : 0.f;
    }
}

__global__ void zero_kernel(float* __restrict__ p, int n)
{
    int i = blockIdx.x * blockDim.x + threadIdx.x;
    if (i < n) p[i] = 0.f;
}

// ---------------- host side ----------------
static inline void gemm(const float* A, int Ars, int Acs,
                        const float* B, int Brs, int Bcs,
                        float* C, long Crs, long Ccs,
                        int Md, int Nd, int Kd, int epi,
                        const float* e0 = nullptr, const float* e1 = nullptr,
                        const float* e2 = nullptr, float* o1 = nullptr, int mod = 1)
{
    dim3 grid((Nd + TN - 1) / TN, (Md + TM - 1) / TM);
    sgemm<<<grid, 256>>>(A, Ars, Acs, B, Brs, Bcs, C, Crs, Ccs,
                         Md, Nd, Kd, epi, e0, e1, e2, o1, mod);
}

extern "C" void kernel_launch(void* const* d_in, const int* in_sizes, int n_in,
                              void* d_out, int out_size)
{
    const float* X0   = (const float*)d_in[0];   // [32, 1024]
    const float* W1   = (const float*)d_in[1];   // [32, 512]
    const float* b1   = (const float*)d_in[2];   // [512]
    const float* W2   = (const float*)d_in[3];   // [512, 512]
    const float* b2   = (const float*)d_in[4];   // [512]
    const float* W3   = (const float*)d_in[5];   // [512, 400]
    const float* b3   = (const float*)d_in[6];   // [400]
    const float* ubar = (const float*)d_in[7];   // [8, 1]
    const float* F    = (const float*)d_in[8];   // [800, 400]
    const float* gg   = (const float*)d_in[9];   // [800]
    const float* H0   = (const float*)d_in[10];  // [800, 32]
    float* out = (float*)d_out;                  // [400, 1024]

    float *pH1, *pH2, *pV, *pB, *pK, *pXa, *pXb, *pT, *pFK, *pG, *pC, *pWa, *pWb, *pY, *pU;
    cudaGetSymbolAddress((void**)&pH1, dH1);
    cudaGetSymbolAddress((void**)&pH2, dH2);
    cudaGetSymbolAddress((void**)&pV,  dV);
    cudaGetSymbolAddress((void**)&pB,  dBc);
    cudaGetSymbolAddress((void**)&pK,  dK);
    cudaGetSymbolAddress((void**)&pXa, dXa);
    cudaGetSymbolAddress((void**)&pXb, dXb);
    cudaGetSymbolAddress((void**)&pT,  dT);
    cudaGetSymbolAddress((void**)&pFK, dFK);
    cudaGetSymbolAddress((void**)&pG,  dG);
    cudaGetSymbolAddress((void**)&pC,  dCm);
    cudaGetSymbolAddress((void**)&pWa, dWa);
    cudaGetSymbolAddress((void**)&pWb, dWb);
    cudaGetSymbolAddress((void**)&pY,  dY);
    cudaGetSymbolAddress((void**)&pU,  dU);

    // 1) MLP head: V = tanh(relu(relu(X0^T W1 + b1) W2 + b2) W3 + b3) * ubar[j%8]
    gemm(X0, 1, NB,   W1, HIDD, 1, pH1, HIDD, 1, NB, HIDD, NN,   1, b1);
    gemm(pH1, HIDD, 1, W2, HIDD, 1, pH2, HIDD, 1, NB, HIDD, HIDD, 1, b2);
    gemm(pH2, HIDD, 1, W3, DD,   1, pV,  DD,   1, NB, DD,   HIDD, 2, b3, ubar, nullptr, nullptr, MMOD);

    // 2) b = g + X0^T @ H0^T
    gemm(X0, 1, NB, H0, 1, NN, pB, NC, 1, NB, NC, NN, 3, gg);

    // 3) K = 2I + F^T F
    gemm(F, 1, DD, F, DD, 1, pK, DD, 1, DD, DD, NC, 7);

    // 4) Kinv via Newton-Schulz: X <- 2X - X K X, X0 = (2/(2+gersh)) I
    gershgorin_kernel<<<1, 512>>>(pK, DD);
    init_diag_kernel<<<(DD * DD + 255) / 256, 256>>>(pXa, DD);
    {
        float* Xc = pXa; float* Xn = pXb;
        for (int t = 0; t < NEWTON_ITERS; t++) {
            gemm(pK, DD, 1, Xc, DD, 1, pT, DD, 1, DD, DD, DD, 0);           // T = K X
            gemm(Xc, DD, 1, pT, DD, 1, Xn, DD, 1, DD, DD, DD, 8, Xc);      // Xn = 2X - X T
            float* tmp = Xc; Xc = Xn; Xn = tmp;
        }
        // NEWTON_ITERS even -> Kinv in pXa
    }

    // 5) precompute FK = F Kinv, G = FK F^T, C = 2 V FK^T
    gemm(F,   DD, 1, pXa, DD, 1, pFK, DD, 1, NC, DD, DD, 0);
    gemm(pFK, DD, 1, F,   1, DD, pG,  NC, 1, NC, NC, DD, 0);
    gemm(pV,  DD, 1, pFK, 1, DD, pC,  NC, 1, NB, NC, DD, 6);

    // 6) init: w0 = min(V F^T, b), y0 = 0
    gemm(pV, DD, 1, F, 1, DD, pWa, NC, 1, NB, NC, DD, 4, pB);
    zero_kernel<<<(NB * NC + 255) / 256, 256>>>(pY, NB * NC);

    // 7) ADMM: s = C + y + w G ; y = max(s-b,0) ; w = s - 2y
    {
        float* wc = pWa; float* wn = pWb;
        for (int t = 0; t < ADMM_ITERS; t++) {
            gemm(wc, NC, 1, pG, NC, 1, wn, NC, 1, NB, NC, NC, 5, pC, pY, pB, pY);
            float* tmp = wc; wc = wn; wn = tmp;
        }
        // ADMM_ITERS even -> final w in pWa
    }

    // 8) u = 2 V Kinv + w FK ; out = u^T  [400, 1024]
    gemm(pV,  DD, 1, pXa, DD, 1, pU, DD, 1, NB, DD, DD, 6);
    gemm(pWa, NC, 1, pFK, DD, 1, out, 1, NB, NB, DD, NC, 9, pU);
}

// round 4
// speedup vs baseline: 1.5960x; 1.5960x over previous
#include <cuda_runtime.h>
#include <cuda_bf16.h>
#include <math.h>
#include <stdint.h>

#define NB   1024
#define NN   32
#define HIDD 512
#define DD   400
#define NC   800
#define ADMM_ITERS 40
#define NEWTON_ITERS 8

typedef __nv_bfloat16 bf;

// ---------------- device scratch ----------------
__device__ float g_alpha;
__device__ float dKf[DD*DD];
__device__ float dXaf[DD*DD], dXbf[DD*DD];
__device__ float dFKf[NC*DD];
__device__ float dCf_[NB*NC];
__device__ float dbf_[NB*NC];
__device__ float dyf_[NB*NC];
__device__ float dUf_[NB*DD];

__device__ bf X0Th[NB*NN], X0Tl[NB*NN];
__device__ bf W1Th[HIDD*NN], W1Tl[HIDD*NN];
__device__ bf W2Th[HIDD*HIDD], W2Tl[HIDD*HIDD];
__device__ bf W3Th[DD*HIDD], W3Tl[DD*HIDD];
__device__ bf H0h_[NC*NN], H0l_[NC*NN];
__device__ bf Fh_[NC*DD], Fl_[NC*DD];
__device__ bf FTh_[DD*NC], FTl_[DD*NC];
__device__ bf H1h_[NB*HIDD], H1l_[NB*HIDD];
__device__ bf H2h_[NB*HIDD], H2l_[NB*HIDD];
__device__ bf Vh_[NB*DD], Vl_[NB*DD];
__device__ bf Kh_[DD*DD], Kl_[DD*DD];
__device__ bf Xah_[DD*DD], Xal_[DD*DD];
__device__ bf Xbh_[DD*DD], Xbl_[DD*DD];
__device__ bf Yh_[DD*DD], Yl_[DD*DD];
__device__ bf FKh_[NC*DD], FKl_[NC*DD];
__device__ bf FKTh_[DD*NC], FKTl_[DD*NC];
__device__ bf Gh_[NC*NC], Gl_[NC*NC];
__device__ bf Wah_[NB*NC], Wal_[NB*NC];
__device__ bf Wbh_[NB*NC], Wbl_[NB*NC];

// ---------------- PTX helpers ----------------
__device__ __forceinline__ uint32_t smem_u32(const void* p) {
    uint32_t a;
    asm("{ .reg .u64 t; cvta.to.shared.u64 t, %1; cvt.u32.u64 %0, t; }" : "=r"(a) : "l"(p));
    return a;
}
__device__ __forceinline__ void cp16(uint32_t sa, const void* g, int bytes) {
    asm volatile("cp.async.cg.shared.global [%0], [%1], 16, %2;"
                 :: "r"(sa), "l"(g), "r"(bytes) : "memory");
}
#define CP_COMMIT() asm volatile("cp.async.commit_group;" ::: "memory")
#define CP_WAIT2()  asm volatile("cp.async.wait_group 2;" ::: "memory")
#define CP_WAIT0()  asm volatile("cp.async.wait_group 0;" ::: "memory")

__device__ __forceinline__ void ldsm4(uint32_t& r0, uint32_t& r1, uint32_t& r2, uint32_t& r3,
                                      uint32_t a) {
    asm volatile("ldmatrix.sync.aligned.m8n8.x4.shared.b16 {%0,%1,%2,%3}, [%4];"
                 : "=r"(r0), "=r"(r1), "=r"(r2), "=r"(r3) : "r"(a));
}
__device__ __forceinline__ void mma16816(float* c, const uint32_t* a, const uint32_t* b) {
    asm volatile("mma.sync.aligned.m16n8k16.row.col.f32.bf16.bf16.f32 "
                 "{%0,%1,%2,%3},{%4,%5,%6,%7},{%8,%9},{%0,%1,%2,%3};"
                 : "+f"(c[0]), "+f"(c[1]), "+f"(c[2]), "+f"(c[3])
                 : "r"(a[0]), "r"(a[1]), "r"(a[2]), "r"(a[3]), "r"(b[0]), "r"(b[1]));
}

// ---------------- tensor GEMM: C[M,N] = epi( A[M,K] @ Bt[N,K]^T ) ----------------
// A,B as bf16 hi/lo pairs; products AhBh + AhBl + AlBh accumulated in fp32.
// MT = m16 tiles per warp (BM = MT*32). BN=64, BK=16, 4-stage cp.async pipeline.
#define SROW 24          // smem row stride in bf16 elems (48 B) -> conflict-free ldmatrix

template <int MT>
__global__ __launch_bounds__(256) void tgemm(
    const bf* __restrict__ Ah, const bf* __restrict__ Al,
    const bf* __restrict__ Bh, const bf* __restrict__ Bl,
    float* __restrict__ Cf, bf* __restrict__ Ch, bf* __restrict__ Cl,
    long Crs, long Ccs,
    int Md, int Nd, int Kd,
    int epi, const float* __restrict__ e0, const float* __restrict__ e1,
    const float* __restrict__ e2, float* __restrict__ o1)
{
    constexpr int BMc = MT * 32;
    constexpr int A_HALF = BMc * SROW * 2;       // bytes, one matrix (hi or lo)
    constexpr int B_HALF = 64 * SROW * 2;
    constexpr int STAGE = 2 * A_HALF + 2 * B_HALF;

    extern __shared__ char sm[];
    const uint32_t sbase = smem_u32(sm);
    const int tid = threadIdx.x;
    const int wid = tid >> 5, lane = tid & 31;
    const int wm = wid >> 2, wn = wid & 3;
    const int i0 = blockIdx.y * BMc, j0 = blockIdx.x * 64;
    const int nch = Kd >> 4;

    auto fill = [&](int c) {
        const uint32_t st = sbase + (c & 3) * STAGE;
        const int k0 = c << 4;
#pragma unroll
        for (int t = 0; t < BMc / 64; t++) {
            int idx = tid + t * 256;
            int half = idx & 1, row = idx >> 1;
            int mat = row / BMc, r = row & (BMc - 1);
            int gi = i0 + r, gk = k0 + half * 8;
            bool ok = gi < Md;
            const bf* src = (mat ? Al : Ah) + (long)gi * Kd + gk;
            cp16(st + mat * A_HALF + r * 48 + half * 16,
                 ok ? (const void*)src : (const void*)Ah, ok ? 16 : 0);
        }
        {
            int half = tid & 1, row = tid >> 1;
            int mat = row >> 6, r = row & 63;
            int gj = j0 + r, gk = k0 + half * 8;
            bool ok = gj < Nd;
            const bf* src = (mat ? Bl : Bh) + (long)gj * Kd + gk;
            cp16(st + 2 * A_HALF + mat * B_HALF + r * 48 + half * 16,
                 ok ? (const void*)src : (const void*)Bh, ok ? 16 : 0);
        }
    };

    float acc[MT][2][4];
#pragma unroll
    for (int a = 0; a < MT; a++)
#pragma unroll
        for (int b = 0; b < 2; b++)
#pragma unroll
            for (int r = 0; r < 4; r++) acc[a][b][r] = 0.f;

    // per-thread ldmatrix offsets (within a stage)
    const uint32_t aoff = (uint32_t)((wm * (BMc / 2) + (lane & 15)) * 48 + (lane >> 4) * 16);
    const uint32_t boff = (uint32_t)(2 * A_HALF + (wn * 16 + (lane & 15)) * 48 + (lane >> 4) * 16);

    // prologue: 3 stages in flight
#pragma unroll
    for (int t = 0; t < 3; t++) { if (t < nch) fill(t); CP_COMMIT(); }

    for (int c = 0; c < nch; c++) {
        CP_WAIT2();
        __syncthreads();
        if (c + 3 < nch) fill(c + 3);
        CP_COMMIT();

        const uint32_t st = sbase + (c & 3) * STAGE;
        uint32_t bhf[2][2], blf[2][2];
        {
            uint32_t r0, r1, r2, r3;
            ldsm4(r0, r1, r2, r3, st + boff);
            bhf[0][0] = r0; bhf[0][1] = r2; bhf[1][0] = r1; bhf[1][1] = r3;
            ldsm4(r0, r1, r2, r3, st + boff + B_HALF);
            blf[0][0] = r0; blf[0][1] = r2; blf[1][0] = r1; blf[1][1] = r3;
        }
#pragma unroll
        for (int mt = 0; mt < MT; mt++) {
            uint32_t ahf[4], alf[4];
            ldsm4(ahf[0], ahf[1], ahf[2], ahf[3], st + aoff + mt * 16 * 48);
            ldsm4(alf[0], alf[1], alf[2], alf[3], st + aoff + mt * 16 * 48 + A_HALF);
#pragma unroll
            for (int nt = 0; nt < 2; nt++) {
                mma16816(acc[mt][nt], ahf, bhf[nt]);
                mma16816(acc[mt][nt], ahf, blf[nt]);
                mma16816(acc[mt][nt], alf, bhf[nt]);
            }
        }
    }

    // ---------------- epilogue ----------------
    const int rbase = i0 + wm * (BMc / 2) + (lane >> 2);
    const int cb = j0 + wn * 16 + (lane & 3) * 2;
#pragma unroll
    for (int mt = 0; mt < MT; mt++) {
#pragma unroll
        for (int nt = 0; nt < 2; nt++) {
#pragma unroll
            for (int rr = 0; rr < 2; rr++) {
#pragma unroll
                for (int cc = 0; cc < 2; cc++) {
                    int i = rbase + mt * 16 + rr * 8;
                    int j = cb + nt * 8 + cc;
                    if (i >= Md || j >= Nd) continue;
                    float v = acc[mt][nt][rr * 2 + cc];
                    long rm = (long)i * Nd + j;
                    float out;
                    switch (epi) {
                        default:
                        case 0: out = v; break;
                        case 1: out = fmaxf(v + e0[j], 0.f); break;
                        case 2: out = tanhf(v + e0[j]) * e1[j & 7]; break;
                        case 3: out = v + e0[j]; break;
                        case 4: out = fminf(v, e0[rm]); break;
                        case 5: {
                            float s = v + e0[rm] + e1[rm];
                            float yn = fmaxf(s - e2[rm], 0.f);
                            o1[rm] = yn;
                            out = s - 2.f * yn;
                        } break;
                        case 6: out = 2.f * v; break;
                        case 7: out = (i == j) ? v + 2.f : v; break;
                        case 8: out = 2.f * e0[rm] - v; break;
                        case 9: out = v + e0[rm]; break;
                    }
                    if (Cf) Cf[(long)i * Crs + (long)j * Ccs] = out;
                    if (Ch) {
                        bf h16 = __float2bfloat16(out);
                        Ch[rm] = h16;
                        Cl[rm] = __float2bfloat16(out - __bfloat162float(h16));
                    }
                }
            }
        }
    }
    CP_WAIT0();   // retire any tail (possibly empty) groups before exit
}

// ---------------- small kernels ----------------
__global__ void split_kernel(const float* __restrict__ s, bf* __restrict__ h,
                             bf* __restrict__ l, int n) {
    int i = blockIdx.x * blockDim.x + threadIdx.x;
    if (i < n) {
        float x = s[i];
        bf b = __float2bfloat16(x);
        h[i] = b;
        l[i] = __float2bfloat16(x - __bfloat162float(b));
    }
}
__global__ void transpose_split(const float* __restrict__ s, bf* __restrict__ h,
                                bf* __restrict__ l, int R, int C) {
    int i = blockIdx.x * blockDim.x + threadIdx.x;
    if (i < R * C) {
        int r = i / C, c = i - r * C;
        float x = s[i];
        bf b = __float2bfloat16(x);
        h[c * R + r] = b;
        l[c * R + r] = __float2bfloat16(x - __bfloat162float(b));
    }
}
__global__ void gershgorin_kernel(const float* __restrict__ K, int n) {
    __shared__ float red[512];
    float mx = 0.f;
    for (int i = threadIdx.x; i < n; i += blockDim.x) {
        float sum = 0.f;
        for (int j = 0; j < n; j++) sum += fabsf(K[i * n + j]);
        mx = fmaxf(mx, sum);
    }
    red[threadIdx.x] = mx;
    __syncthreads();
    for (int s = 256; s > 0; s >>= 1) {
        if (threadIdx.x < s) red[threadIdx.x] = fmaxf(red[threadIdx.x], red[threadIdx.x + s]);
        __syncthreads();
    }
    if (threadIdx.x == 0) g_alpha = 2.f / (2.f + red[0]);
}
__global__ void init_diag_split(float* __restrict__ Xf, bf* __restrict__ Xh,
                                bf* __restrict__ Xl, int n) {
    int idx = blockIdx.x * blockDim.x + threadIdx.x;
    if (idx < n * n) {
        int i = idx / n, j = idx - i * n;
        float v = (i == j) ? g_alpha : 0.f;
        Xf[idx] = v;
        bf b = __float2bfloat16(v);
        Xh[idx] = b;
        Xl[idx] = __float2bfloat16(v - __bfloat162float(b));
    }
}
__global__ void zero_kernel(float* __restrict__ p, int n) {
    int i = blockIdx.x * blockDim.x + threadIdx.x;
    if (i < n) p[i] = 0.f;
}

// ---------------- host ----------------
template <int MT>
static inline void tg(const bf* Ah, const bf* Al, const bf* Bh, const bf* Bl,
                      float* Cf, bf* Ch, bf* Cl, long Crs, long Ccs,
                      int M, int N, int K, int epi,
                      const float* e0 = nullptr, const float* e1 = nullptr,
                      const float* e2 = nullptr, float* o1 = nullptr)
{
    constexpr int BMc = MT * 32;
    constexpr int SMEMB = 4 * (2 * BMc * SROW * 2 + 2 * 64 * SROW * 2);
    dim3 grid((N + 63) / 64, (M + BMc - 1) / BMc);
    tgemm<MT><<<grid, 256, SMEMB>>>(Ah, Al, Bh, Bl, Cf, Ch, Cl, Crs, Ccs,
                                    M, N, K, epi, e0, e1, e2, o1);
}

template <typename T> static inline T* sym(const void* s) {
    void* p = nullptr;
    cudaGetSymbolAddress(&p, s);
    return (T*)p;
}

extern "C" void kernel_launch(void* const* d_in, const int* in_sizes, int n_in,
                              void* d_out, int out_size)
{
    const float* X0   = (const float*)d_in[0];   // [32, 1024]
    const float* W1   = (const float*)d_in[1];   // [32, 512]
    const float* b1   = (const float*)d_in[2];
    const float* W2   = (const float*)d_in[3];   // [512, 512]
    const float* b2   = (const float*)d_in[4];
    const float* W3   = (const float*)d_in[5];   // [512, 400]
    const float* b3   = (const float*)d_in[6];
    const float* ubar = (const float*)d_in[7];   // [8]
    const float* F    = (const float*)d_in[8];   // [800, 400]
    const float* gg   = (const float*)d_in[9];   // [800]
    const float* H0   = (const float*)d_in[10];  // [800, 32]
    float* out = (float*)d_out;                  // [400, 1024]

    cudaFuncSetAttribute(tgemm<4>, cudaFuncAttributeMaxDynamicSharedMemorySize,
                         4 * (2 * 128 * SROW * 2 + 2 * 64 * SROW * 2));
    cudaFuncSetAttribute(tgemm<2>, cudaFuncAttributeMaxDynamicSharedMemorySize,
                         4 * (2 * 64 * SROW * 2 + 2 * 64 * SROW * 2));

    float *pKf = sym<float>(dKf), *pXaf = sym<float>(dXaf), *pXbf = sym<float>(dXbf);
    float *pFKf = sym<float>(dFKf), *pCf = sym<float>(dCf_), *pbf = sym<float>(dbf_);
    float *pyf = sym<float>(dyf_), *pUf = sym<float>(dUf_);

    bf *x0th = sym<bf>(X0Th), *x0tl = sym<bf>(X0Tl);
    bf *w1th = sym<bf>(W1Th), *w1tl = sym<bf>(W1Tl);
    bf *w2th = sym<bf>(W2Th), *w2tl = sym<bf>(W2Tl);
    bf *w3th = sym<bf>(W3Th), *w3tl = sym<bf>(W3Tl);
    bf *h0h = sym<bf>(H0h_), *h0l = sym<bf>(H0l_);
    bf *fh = sym<bf>(Fh_), *fl = sym<bf>(Fl_);
    bf *fth = sym<bf>(FTh_), *ftl = sym<bf>(FTl_);
    bf *h1h = sym<bf>(H1h_), *h1l = sym<bf>(H1l_);
    bf *h2h = sym<bf>(H2h_), *h2l = sym<bf>(H2l_);
    bf *vh = sym<bf>(Vh_), *vl = sym<bf>(Vl_);
    bf *kh = sym<bf>(Kh_), *kl = sym<bf>(Kl_);
    bf *xah = sym<bf>(Xah_), *xal = sym<bf>(Xal_);
    bf *xbh = sym<bf>(Xbh_), *xbl = sym<bf>(Xbl_);
    bf *yh = sym<bf>(Yh_), *yl = sym<bf>(Yl_);
    bf *fkh = sym<bf>(FKh_), *fkl = sym<bf>(FKl_);
    bf *fkth = sym<bf>(FKTh_), *fktl = sym<bf>(FKTl_);
    bf *ghh = sym<bf>(Gh_), *gll = sym<bf>(Gl_);
    bf *wah = sym<bf>(Wah_), *wal = sym<bf>(Wal_);
    bf *wbh = sym<bf>(Wbh_), *wbl = sym<bf>(Wbl_);

    // ---- operand prep ----
    transpose_split<<<(NN*NB + 255)/256, 256>>>(X0, x0th, x0tl, NN, NB);
    transpose_split<<<(NN*HIDD + 255)/256, 256>>>(W1, w1th, w1tl, NN, HIDD);
    transpose_split<<<(HIDD*HIDD + 255)/256, 256>>>(W2, w2th, w2tl, HIDD, HIDD);
    transpose_split<<<(HIDD*DD + 255)/256, 256>>>(W3, w3th, w3tl, HIDD, DD);
    split_kernel<<<(NC*NN + 255)/256, 256>>>(H0, h0h, h0l, NC*NN);
    split_kernel<<<(NC*DD + 255)/256, 256>>>(F, fh, fl, NC*DD);
    transpose_split<<<(NC*DD + 255)/256, 256>>>(F, fth, ftl, NC, DD);

    // ---- MLP head -> V (split) ----
    tg<4>(x0th, x0tl, w1th, w1tl, nullptr, h1h, h1l, HIDD, 1, NB, HIDD, NN, 1, b1);
    tg<4>(h1h, h1l, w2th, w2tl, nullptr, h2h, h2l, HIDD, 1, NB, HIDD, HIDD, 1, b2);
    tg<4>(h2h, h2l, w3th, w3tl, nullptr, vh, vl, DD, 1, NB, DD, HIDD, 2, b3, ubar);

    // ---- b = g + X0^T H0^T ----
    tg<4>(x0th, x0tl, h0h, h0l, pbf, nullptr, nullptr, NC, 1, NB, NC, NN, 3, gg);

    // ---- K = 2I + F^T F ----
    tg<2>(fth, ftl, fth, ftl, pKf, kh, kl, DD, 1, DD, DD, NC, 7);

    // ---- Kinv: Newton-Schulz ----
    gershgorin_kernel<<<1, 512>>>(pKf, DD);
    init_diag_split<<<(DD*DD + 255)/256, 256>>>(pXaf, xah, xal, DD);
    {
        float *Xcf = pXaf, *Xnf = pXbf;
        bf *Xch = xah, *Xcl = xal, *Xnh = xbh, *Xnl = xbl;
        for (int t = 0; t < NEWTON_ITERS; t++) {
            tg<2>(Xch, Xcl, kh, kl, nullptr, yh, yl, DD, 1, DD, DD, DD, 0);      // Y = X K
            tg<2>(yh, yl, Xch, Xcl, Xnf, Xnh, Xnl, DD, 1, DD, DD, DD, 8, Xcf);   // Xn = 2X - Y X
            float* tf = Xcf; Xcf = Xnf; Xnf = tf;
            bf* t1 = Xch; Xch = Xnh; Xnh = t1;
            bf* t2 = Xcl; Xcl = Xnl; Xnl = t2;
        }
        // even iters -> Kinv in xah/xal, pXaf
    }

    // ---- precompute: FK, FKT, G, C ----
    tg<2>(fh, fl, xah, xal, pFKf, fkh, fkl, DD, 1, NC, DD, DD, 0);            // FK = F Kinv
    transpose_split<<<(NC*DD + 255)/256, 256>>>(pFKf, fkth, fktl, NC, DD);
    tg<4>(fkh, fkl, fh, fl, nullptr, ghh, gll, NC, 1, NC, NC, DD, 0);         // G = FK F^T
    tg<4>(vh, vl, fkh, fkl, pCf, nullptr, nullptr, NC, 1, NB, NC, DD, 6);     // C = 2 V FK^T

    // ---- init: w0 = min(V F^T, b), y = 0 ----
    tg<4>(vh, vl, fh, fl, nullptr, wah, wal, NC, 1, NB, NC, DD, 4, pbf);
    zero_kernel<<<(NB*NC + 255)/256, 256>>>(pyf, NB * NC);

    // ---- ADMM: s = C + y + w G ; y = max(s-b,0) ; w = s - 2y ----
    {
        bf *wch = wah, *wcl = wal, *wnh = wbh, *wnl = wbl;
        for (int t = 0; t < ADMM_ITERS; t++) {
            tg<4>(wch, wcl, ghh, gll, nullptr, wnh, wnl, NC, 1,
                  NB, NC, NC, 5, pCf, pyf, pbf, pyf);
            bf* t1 = wch; wch = wnh; wnh = t1;
            bf* t2 = wcl; wcl = wnl; wnl = t2;
        }
        // even iters -> final w in wah/wal
    }

    // ---- u = 2 V Kinv + w FK ; out = u^T ----
    tg<4>(vh, vl, xah, xal, pUf, nullptr, nullptr, DD, 1, NB, DD, DD, 6);
    tg<4>(wah, wal, fkth, fktl, out, nullptr, nullptr, 1, NB, NB, DD, NC, 9, pUf);
}

// round 8
// speedup vs baseline: 2.0864x; 1.3073x over previous
#include <cuda_runtime.h>
#include <cuda_bf16.h>
#include <math.h>
#include <stdint.h>

#define NB   1024
#define NN   32
#define HIDD 512
#define DD   400
#define NC   800
#define ADMM_ITERS 40
#define NEWTON_ITERS 8

typedef __nv_bfloat16 bf;

// ---------------- device scratch ----------------
__device__ float g_alpha;
__device__ float dKf[DD*DD];
__device__ float dXaf[DD*DD], dXbf[DD*DD];
__device__ float dFKf[NC*DD];
__device__ float dCf_[NB*NC];
__device__ float dbf_[NB*NC];
__device__ float dyf_[NB*NC];
__device__ float dUf_[NB*DD];

__device__ bf X0Th[NB*NN], X0Tl[NB*NN];
__device__ bf W1Th[HIDD*NN], W1Tl[HIDD*NN];
__device__ bf W2Th[HIDD*HIDD], W2Tl[HIDD*HIDD];
__device__ bf W3Th[DD*HIDD], W3Tl[DD*HIDD];
__device__ bf H0h_[NC*NN], H0l_[NC*NN];
__device__ bf Fh_[NC*DD], Fl_[NC*DD];
__device__ bf FTh_[DD*NC], FTl_[DD*NC];
__device__ bf H1h_[NB*HIDD], H1l_[NB*HIDD];
__device__ bf H2h_[NB*HIDD], H2l_[NB*HIDD];
__device__ bf Vh_[NB*DD], Vl_[NB*DD];
__device__ bf Kh_[DD*DD], Kl_[DD*DD];
__device__ bf Xah_[DD*DD], Xal_[DD*DD];
__device__ bf Xbh_[DD*DD], Xbl_[DD*DD];
__device__ bf Yh_[DD*DD], Yl_[DD*DD];
__device__ bf FKh_[NC*DD], FKl_[NC*DD];
__device__ bf FKTh_[DD*NC], FKTl_[DD*NC];
__device__ bf Gh_[NC*NC], Gl_[NC*NC];
__device__ bf Wah_[NB*NC], Wal_[NB*NC];
__device__ bf Wbh_[NB*NC], Wbl_[NB*NC];

// ---------------- PTX helpers ----------------
__device__ __forceinline__ uint32_t smem_u32(const void* p) {
    uint32_t a;
    asm("{ .reg .u64 t; cvta.to.shared.u64 t, %1; cvt.u32.u64 %0, t; }" : "=r"(a) : "l"(p));
    return a;
}
__device__ __forceinline__ void cp16(uint32_t sa, const void* g, int bytes) {
    asm volatile("cp.async.cg.shared.global [%0], [%1], 16, %2;"
                 :: "r"(sa), "l"(g), "r"(bytes) : "memory");
}
#define CP_COMMIT() asm volatile("cp.async.commit_group;" ::: "memory")
#define CP_WAIT1()  asm volatile("cp.async.wait_group 1;" ::: "memory")
#define CP_WAIT0()  asm volatile("cp.async.wait_group 0;" ::: "memory")

__device__ __forceinline__ void ldsm4(uint32_t& r0, uint32_t& r1, uint32_t& r2, uint32_t& r3,
                                      uint32_t a) {
    asm volatile("ldmatrix.sync.aligned.m8n8.x4.shared.b16 {%0,%1,%2,%3}, [%4];"
                 : "=r"(r0), "=r"(r1), "=r"(r2), "=r"(r3) : "r"(a));
}
__device__ __forceinline__ void mma16816(float* c, const uint32_t* a, const uint32_t* b) {
    asm volatile("mma.sync.aligned.m16n8k16.row.col.f32.bf16.bf16.f32 "
                 "{%0,%1,%2,%3},{%4,%5,%6,%7},{%8,%9},{%0,%1,%2,%3};"
                 : "+f"(c[0]), "+f"(c[1]), "+f"(c[2]), "+f"(c[3])
                 : "r"(a[0]), "r"(a[1]), "r"(a[2]), "r"(a[3]), "r"(b[0]), "r"(b[1]));
}
#define SWZ(x) ((x) ^ (((x) >> 3) & 0x70))

// ---------------- tensor GEMM: C[M,N] = epi( A[M,K] @ Bt[N,K]^T ) ----------------
// bf16 hi/lo split (AhBh + AhBl + AlBh), fp32 accum. BK=64, SW128 smem, 3 stages.
template <int MT>     // BM = MT*32 ; warp tile = (MT*16) x 16 ; 8 warps (2 x 4)
__global__ __launch_bounds__(256, 1) void tgemm(
    const bf* __restrict__ Ah, const bf* __restrict__ Al,
    const bf* __restrict__ Bh, const bf* __restrict__ Bl,
    float* __restrict__ Cf, bf* __restrict__ Ch, bf* __restrict__ Cl,
    long Crs, long Ccs,
    int Md, int Nd, int Kd,
    int epi, const float* __restrict__ e0, const float* __restrict__ e1,
    const float* __restrict__ e2, float* __restrict__ o1)
{
    constexpr int BMc = MT * 32;
    constexpr int A_HALF = BMc * 128;      // bytes: BMc rows x 128B (64 bf16)
    constexpr int B_HALF = 64 * 128;
    constexpr int STAGE = 2 * A_HALF + 2 * B_HALF;

    extern __shared__ char sm[];
    const uint32_t sbase = smem_u32(sm);
    const int tid = threadIdx.x;
    const int wid = tid >> 5, lane = tid & 31;
    const int wm = wid >> 2, wn = wid & 3;
    const int i0 = blockIdx.y * BMc, j0 = blockIdx.x * 64;
    const int nch = (Kd + 63) >> 6;

    auto fill = [&](int c) {
        const uint32_t st = sbase + (c % 3) * STAGE;
        const int k0 = c << 6;
        // A: 2 mats * BMc rows * 8 segs of 16B
#pragma unroll
        for (int t = 0; t < BMc / 16; t++) {
            int idx = tid + t * 256;
            int seg = idx & 7, r = (idx >> 3) & (BMc - 1);
            int mat = idx >= 8 * BMc;
            int gi = i0 + r, gk = k0 + seg * 8;
            bool ok = (gi < Md) && (gk < Kd);
            const bf* src = (mat ? Al : Ah) + (long)gi * Kd + gk;
            cp16(st + mat * A_HALF + SWZ((uint32_t)(r * 128 + seg * 16)),
                 ok ? (const void*)src : (const void*)Ah, ok ? 16 : 0);
        }
        // B: 2 mats * 64 rows * 8 segs
#pragma unroll
        for (int t = 0; t < 4; t++) {
            int idx = tid + t * 256;
            int seg = idx & 7, r = (idx >> 3) & 63;
            int mat = idx >> 9;
            int gj = j0 + r, gk = k0 + seg * 8;
            bool ok = (gj < Nd) && (gk < Kd);
            const bf* src = (mat ? Bl : Bh) + (long)gj * Kd + gk;
            cp16(st + 2 * A_HALF + mat * B_HALF + SWZ((uint32_t)(r * 128 + seg * 16)),
                 ok ? (const void*)src : (const void*)Bh, ok ? 16 : 0);
        }
    };

    float acc[MT][2][4];
#pragma unroll
    for (int a = 0; a < MT; a++)
#pragma unroll
        for (int b = 0; b < 2; b++)
#pragma unroll
            for (int r = 0; r < 4; r++) acc[a][b][r] = 0.f;

    // unswizzled per-lane byte offsets (row part); k part added per ks
    const uint32_t arow = (uint32_t)((wm * (BMc / 2) + (lane & 15)) * 128 + (lane >> 4) * 16);
    const uint32_t brow = (uint32_t)((wn * 16 + (lane & 15)) * 128 + (lane >> 4) * 16);

    fill(0); CP_COMMIT();
    if (nch > 1) fill(1);
    CP_COMMIT();

    for (int c = 0; c < nch; c++) {
        CP_WAIT1();
        __syncthreads();
        if (c + 2 < nch) fill(c + 2);
        CP_COMMIT();

        const uint32_t st = sbase + (c % 3) * STAGE;
#pragma unroll
        for (int ks = 0; ks < 4; ks++) {
            uint32_t bhf[2][2], blf[2][2];
            {
                uint32_t r0, r1, r2, r3;
                ldsm4(r0, r1, r2, r3, st + 2 * A_HALF + SWZ(brow + ks * 32));
                bhf[0][0] = r0; bhf[0][1] = r2; bhf[1][0] = r1; bhf[1][1] = r3;
                ldsm4(r0, r1, r2, r3, st + 2 * A_HALF + B_HALF + SWZ(brow + ks * 32));
                blf[0][0] = r0; blf[0][1] = r2; blf[1][0] = r1; blf[1][1] = r3;
            }
#pragma unroll
            for (int mt = 0; mt < MT; mt++) {
                uint32_t ahf[4], alf[4];
                ldsm4(ahf[0], ahf[1], ahf[2], ahf[3],
                      st + SWZ(arow + mt * 16 * 128 + ks * 32));
                ldsm4(alf[0], alf[1], alf[2], alf[3],
                      st + A_HALF + SWZ(arow + mt * 16 * 128 + ks * 32));
#pragma unroll
                for (int nt = 0; nt < 2; nt++) {
                    mma16816(acc[mt][nt], ahf, bhf[nt]);
                    mma16816(acc[mt][nt], ahf, blf[nt]);
                    mma16816(acc[mt][nt], alf, bhf[nt]);
                }
            }
        }
    }

    // ---------------- epilogue ----------------
    const int rbase = i0 + wm * (BMc / 2) + (lane >> 2);
    const int cb = j0 + wn * 16 + (lane & 3) * 2;
#pragma unroll
    for (int mt = 0; mt < MT; mt++) {
#pragma unroll
        for (int nt = 0; nt < 2; nt++) {
#pragma unroll
            for (int rr = 0; rr < 2; rr++) {
#pragma unroll
                for (int cc = 0; cc < 2; cc++) {
                    int i = rbase + mt * 16 + rr * 8;
                    int j = cb + nt * 8 + cc;
                    if (i >= Md || j >= Nd) continue;
                    float v = acc[mt][nt][rr * 2 + cc];
                    long rm = (long)i * Nd + j;
                    float out;
                    switch (epi) {
                        default:
                        case 0: out = v; break;
                        case 1: out = fmaxf(v + e0[j], 0.f); break;
                        case 2: out = tanhf(v + e0[j]) * e1[j & 7]; break;
                        case 3: out = v + e0[j]; break;
                        case 4: out = fminf(v, e0[rm]); break;
                        case 5: {
                            float s = v + e0[rm] + e1[rm];
                            float yn = fmaxf(s - e2[rm], 0.f);
                            o1[rm] = yn;
                            out = s - 2.f * yn;
                        } break;
                        case 6: out = 2.f * v; break;
                        case 7: out = (i == j) ? v + 2.f : v; break;
                        case 8: out = 2.f * e0[rm] - v; break;
                        case 9: out = v + e0[rm]; break;
                    }
                    if (Cf) Cf[(long)i * Crs + (long)j * Ccs] = out;
                    if (Ch) {
                        bf h16 = __float2bfloat16(out);
                        Ch[rm] = h16;
                        Cl[rm] = __float2bfloat16(out - __bfloat162float(h16));
                    }
                }
            }
        }
    }
    CP_WAIT0();
}

// ---------------- fused prep kernel (one launch) ----------------
__device__ __forceinline__ void split_one(float x, bf* h, bf* l, long o) {
    bf b = __float2bfloat16(x);
    h[o] = b;
    l[o] = __float2bfloat16(x - __bfloat162float(b));
}
__global__ void prep_all(const float* __restrict__ X0, const float* __restrict__ W1,
                         const float* __restrict__ W2, const float* __restrict__ W3,
                         const float* __restrict__ H0, const float* __restrict__ F,
                         bf* x0th, bf* x0tl, bf* w1th, bf* w1tl, bf* w2th, bf* w2tl,
                         bf* w3th, bf* w3tl, bf* h0h, bf* h0l, bf* fh, bf* fl,
                         bf* fth, bf* ftl)
{
    long idx = (long)blockIdx.x * blockDim.x + threadIdx.x;
    const long n0 = NN * NB, n1 = NN * HIDD, n2 = HIDD * HIDD, n3 = HIDD * DD;
    const long n4 = NC * NN, n5 = (long)NC * DD, n6 = (long)NC * DD;
    if (idx < n0) { // X0 [NN,NB] -> transpose
        int r = idx / NB, c = idx - (long)r * NB;
        split_one(X0[idx], x0th, x0tl, (long)c * NN + r);
        return;
    }
    idx -= n0;
    if (idx < n1) {
        int r = idx / HIDD, c = idx - (long)r * HIDD;
        split_one(W1[idx], w1th, w1tl, (long)c * NN + r);
        return;
    }
    idx -= n1;
    if (idx < n2) {
        int r = idx / HIDD, c = idx - (long)r * HIDD;
        split_one(W2[idx], w2th, w2tl, (long)c * HIDD + r);
        return;
    }
    idx -= n2;
    if (idx < n3) {
        int r = idx / DD, c = idx - (long)r * DD;
        split_one(W3[idx], w3th, w3tl, (long)c * HIDD + r);
        return;
    }
    idx -= n3;
    if (idx < n4) { split_one(H0[idx], h0h, h0l, idx); return; }
    idx -= n4;
    if (idx < n5) { split_one(F[idx], fh, fl, idx); return; }
    idx -= n5;
    if (idx < n6) {
        int r = idx / DD, c = idx - (long)r * DD;
        split_one(F[idx], fth, ftl, (long)c * NC + r);
        return;
    }
}

// ---------------- small kernels ----------------
__global__ void transpose_split(const float* __restrict__ s, bf* __restrict__ h,
                                bf* __restrict__ l, int R, int C) {
    long i = (long)blockIdx.x * blockDim.x + threadIdx.x;
    if (i < (long)R * C) {
        int r = i / C, c = i - (long)r * C;
        split_one(s[i], h, l, (long)c * R + r);
    }
}
__global__ void gershgorin_kernel(const float* __restrict__ K, int n) {
    __shared__ float red[512];
    float mx = 0.f;
    for (int i = threadIdx.x; i < n; i += blockDim.x) {
        float sum = 0.f;
        for (int j = 0; j < n; j++) sum += fabsf(K[i * n + j]);
        mx = fmaxf(mx, sum);
    }
    red[threadIdx.x] = mx;
    __syncthreads();
    for (int s = 256; s > 0; s >>= 1) {
        if (threadIdx.x < s) red[threadIdx.x] = fmaxf(red[threadIdx.x], red[threadIdx.x + s]);
        __syncthreads();
    }
    if (threadIdx.x == 0) g_alpha = 2.f / (2.f + red[0]);
}
__global__ void init_diag_split(float* __restrict__ Xf, bf* __restrict__ Xh,
                                bf* __restrict__ Xl, int n) {
    int idx = blockIdx.x * blockDim.x + threadIdx.x;
    if (idx < n * n) {
        int i = idx / n, j = idx - i * n;
        float v = (i == j) ? g_alpha : 0.f;
        Xf[idx] = v;
        bf b = __float2bfloat16(v);
        Xh[idx] = b;
        Xl[idx] = __float2bfloat16(v - __bfloat162float(b));
    }
}
__global__ void zero_kernel(float* __restrict__ p, int n) {
    int i = blockIdx.x * blockDim.x + threadIdx.x;
    if (i < n) p[i] = 0.f;
}

// ---------------- host ----------------
template <int MT>
static inline void tg(const bf* Ah, const bf* Al, const bf* Bh, const bf* Bl,
                      float* Cf, bf* Ch, bf* Cl, long Crs, long Ccs,
                      int M, int N, int K, int epi,
                      const float* e0 = nullptr, const float* e1 = nullptr,
                      const float* e2 = nullptr, float* o1 = nullptr)
{
    constexpr int BMc = MT * 32;
    constexpr int SMEMB = 3 * (2 * BMc * 128 + 2 * 64 * 128);
    dim3 grid((N + 63) / 64, (M + BMc - 1) / BMc);
    tgemm<MT><<<grid, 256, SMEMB>>>(Ah, Al, Bh, Bl, Cf, Ch, Cl, Crs, Ccs,
                                    M, N, K, epi, e0, e1, e2, o1);
}

template <typename T> static inline T* sym(const void* s) {
    void* p = nullptr;
    cudaGetSymbolAddress(&p, s);
    return (T*)p;
}

extern "C" void kernel_launch(void* const* d_in, const int* in_sizes, int n_in,
                              void* d_out, int out_size)
{
    const float* X0   = (const float*)d_in[0];
    const float* W1   = (const float*)d_in[1];
    const float* b1   = (const float*)d_in[2];
    const float* W2   = (const float*)d_in[3];
    const float* b2   = (const float*)d_in[4];
    const float* W3   = (const float*)d_in[5];
    const float* b3   = (const float*)d_in[6];
    const float* ubar = (const float*)d_in[7];
    const float* F    = (const float*)d_in[8];
    const float* gg   = (const float*)d_in[9];
    const float* H0   = (const float*)d_in[10];
    float* out = (float*)d_out;

    cudaFuncSetAttribute(tgemm<4>, cudaFuncAttributeMaxDynamicSharedMemorySize,
                         3 * (2 * 128 * 128 + 2 * 64 * 128));
    cudaFuncSetAttribute(tgemm<2>, cudaFuncAttributeMaxDynamicSharedMemorySize,
                         3 * (2 * 64 * 128 + 2 * 64 * 128));

    float *pKf = sym<float>(dKf), *pXaf = sym<float>(dXaf), *pXbf = sym<float>(dXbf);
    float *pFKf = sym<float>(dFKf), *pCf = sym<float>(dCf_), *pbf = sym<float>(dbf_);
    float *pyf = sym<float>(dyf_), *pUf = sym<float>(dUf_);

    bf *x0th = sym<bf>(X0Th), *x0tl = sym<bf>(X0Tl);
    bf *w1th = sym<bf>(W1Th), *w1tl = sym<bf>(W1Tl);
    bf *w2th = sym<bf>(W2Th), *w2tl = sym<bf>(W2Tl);
    bf *w3th = sym<bf>(W3Th), *w3tl = sym<bf>(W3Tl);
    bf *h0h = sym<bf>(H0h_), *h0l = sym<bf>(H0l_);
    bf *fh = sym<bf>(Fh_), *fl = sym<bf>(Fl_);
    bf *fth = sym<bf>(FTh_), *ftl = sym<bf>(FTl_);
    bf *h1h = sym<bf>(H1h_), *h1l = sym<bf>(H1l_);
    bf *h2h = sym<bf>(H2h_), *h2l = sym<bf>(H2l_);
    bf *vh = sym<bf>(Vh_), *vl = sym<bf>(Vl_);
    bf *kh = sym<bf>(Kh_), *kl = sym<bf>(Kl_);
    bf *xah = sym<bf>(Xah_), *xal = sym<bf>(Xal_);
    bf *xbh = sym<bf>(Xbh_), *xbl = sym<bf>(Xbl_);
    bf *yh = sym<bf>(Yh_), *yl = sym<bf>(Yl_);
    bf *fkh = sym<bf>(FKh_), *fkl = sym<bf>(FKl_);
    bf *fkth = sym<bf>(FKTh_), *fktl = sym<bf>(FKTl_);
    bf *ghh = sym<bf>(Gh_), *gll = sym<bf>(Gl_);
    bf *wah = sym<bf>(Wah_), *wal = sym<bf>(Wal_);
    bf *wbh = sym<bf>(Wbh_), *wbl = sym<bf>(Wbl_);

    // #0: fused prep
    {
        long total = (long)NN*NB + (long)NN*HIDD + (long)HIDD*HIDD + (long)HIDD*DD
                   + (long)NC*NN + (long)NC*DD + (long)NC*DD;
        prep_all<<<(int)((total + 255) / 256), 256>>>(
            X0, W1, W2, W3, H0, F,
            x0th, x0tl, w1th, w1tl, w2th, w2tl, w3th, w3tl,
            h0h, h0l, fh, fl, fth, ftl);
    }

    // #1-3: MLP head
    tg<4>(x0th, x0tl, w1th, w1tl, nullptr, h1h, h1l, HIDD, 1, NB, HIDD, NN, 1, b1);
    tg<4>(h1h, h1l, w2th, w2tl, nullptr, h2h, h2l, HIDD, 1, NB, HIDD, HIDD, 1, b2);
    tg<4>(h2h, h2l, w3th, w3tl, nullptr, vh, vl, DD, 1, NB, DD, HIDD, 2, b3, ubar);

    // #4: b = g + X0^T H0^T
    tg<4>(x0th, x0tl, h0h, h0l, pbf, nullptr, nullptr, NC, 1, NB, NC, NN, 3, gg);

    // #5: DUMMY ADMM-shaped GEMM for ncu (-s 5 -c 1). Reads scratch, writes dCf_
    // which is fully overwritten by the real C GEMM below. Output-path unaffected.
    tg<4>(wah, wal, ghh, gll, pCf, nullptr, nullptr, NC, 1, NB, NC, NC, 0);

    // K = 2I + F^T F
    tg<2>(fth, ftl, fth, ftl, pKf, kh, kl, DD, 1, DD, DD, NC, 7);

    // Kinv: Newton-Schulz
    gershgorin_kernel<<<1, 512>>>(pKf, DD);
    init_diag_split<<<(DD*DD + 255)/256, 256>>>(pXaf, xah, xal, DD);
    {
        float *Xcf = pXaf, *Xnf = pXbf;
        bf *Xch = xah, *Xcl = xal, *Xnh = xbh, *Xnl = xbl;
        for (int t = 0; t < NEWTON_ITERS; t++) {
            tg<2>(Xch, Xcl, kh, kl, nullptr, yh, yl, DD, 1, DD, DD, DD, 0);
            tg<2>(yh, yl, Xch, Xcl, Xnf, Xnh, Xnl, DD, 1, DD, DD, DD, 8, Xcf);
            float* tf = Xcf; Xcf = Xnf; Xnf = tf;
            bf* t1 = Xch; Xch = Xnh; Xnh = t1;
            bf* t2 = Xcl; Xcl = Xnl; Xnl = t2;
        }
    }

    // precompute: FK, FKT, G, C
    tg<2>(fh, fl, xah, xal, pFKf, fkh, fkl, DD, 1, NC, DD, DD, 0);
    transpose_split<<<(NC*DD + 255)/256, 256>>>(pFKf, fkth, fktl, NC, DD);
    tg<4>(fkh, fkl, fh, fl, nullptr, ghh, gll, NC, 1, NC, NC, DD, 0);
    tg<4>(vh, vl, fkh, fkl, pCf, nullptr, nullptr, NC, 1, NB, NC, DD, 6);

    // init: w0 = min(V F^T, b), y = 0
    tg<4>(vh, vl, fh, fl, nullptr, wah, wal, NC, 1, NB, NC, DD, 4, pbf);
    zero_kernel<<<(NB*NC + 255)/256, 256>>>(pyf, NB * NC);

    // ADMM: s = C + y + w G ; y = max(s-b,0) ; w = s - 2y
    {
        bf *wch = wah, *wcl = wal, *wnh = wbh, *wnl = wbl;
        for (int t = 0; t < ADMM_ITERS; t++) {
            tg<4>(wch, wcl, ghh, gll, nullptr, wnh, wnl, NC, 1,
                  NB, NC, NC, 5, pCf, pyf, pbf, pyf);
            bf* t1 = wch; wch = wnh; wnh = t1;
            bf* t2 = wcl; wcl = wnl; wnl = t2;
        }
    }

    // u = 2 V Kinv + w FK ; out = u^T
    tg<4>(vh, vl, xah, xal, pUf, nullptr, nullptr, DD, 1, NB, DD, DD, 6);
    tg<4>(wah, wal, fkth, fktl, out, nullptr, nullptr, 1, NB, NB, DD, NC, 9, pUf);
}

// round 10
// speedup vs baseline: 2.3904x; 1.1457x over previous
#include <cuda_runtime.h>
#include <cuda_bf16.h>
#include <math.h>
#include <stdint.h>

#define NB   1024
#define NN   32
#define HIDD 512
#define DD   400
#define NC   800
#define ADMM_ITERS 40
#define NEWTON_ITERS 8

typedef __nv_bfloat16 bf;

// ---------------- device scratch ----------------
__device__ float g_alpha;
__device__ float dKf[DD*DD];
__device__ float dXaf[DD*DD], dXbf[DD*DD];
__device__ float dFKf[NC*DD];
__device__ float dCf_[NB*NC];
__device__ float dbf_[NB*NC];
__device__ float dyf_[NB*NC];
__device__ float dUf_[NB*DD];

__device__ bf X0Th[NB*NN], X0Tl[NB*NN];
__device__ bf W1Th[HIDD*NN], W1Tl[HIDD*NN];
__device__ bf W2Th[HIDD*HIDD], W2Tl[HIDD*HIDD];
__device__ bf W3Th[DD*HIDD], W3Tl[DD*HIDD];
__device__ bf H0h_[NC*NN], H0l_[NC*NN];
__device__ bf Fh_[NC*DD], Fl_[NC*DD];
__device__ bf FTh_[DD*NC], FTl_[DD*NC];
__device__ bf H1h_[NB*HIDD], H1l_[NB*HIDD];
__device__ bf H2h_[NB*HIDD], H2l_[NB*HIDD];
__device__ bf Vh_[NB*DD], Vl_[NB*DD];
__device__ bf Kh_[DD*DD], Kl_[DD*DD];
__device__ bf Xah_[DD*DD], Xal_[DD*DD];
__device__ bf Xbh_[DD*DD], Xbl_[DD*DD];
__device__ bf Yh_[DD*DD], Yl_[DD*DD];
__device__ bf FKh_[NC*DD], FKl_[NC*DD];
__device__ bf FKTh_[DD*NC], FKTl_[DD*NC];
__device__ bf Gh_[NC*NC], Gl_[NC*NC];
__device__ bf Wah_[NB*NC], Wal_[NB*NC];
__device__ bf Wbh_[NB*NC], Wbl_[NB*NC];

// ---------------- PTX helpers ----------------
__device__ __forceinline__ uint32_t smem_u32(const void* p) {
    uint32_t a;
    asm("{ .reg .u64 t; cvta.to.shared.u64 t, %1; cvt.u32.u64 %0, t; }" : "=r"(a) : "l"(p));
    return a;
}
__device__ __forceinline__ void cp16(uint32_t sa, const void* g, int bytes) {
    asm volatile("cp.async.cg.shared.global [%0], [%1], 16, %2;"
                 :: "r"(sa), "l"(g), "r"(bytes) : "memory");
}
#define CP_COMMIT() asm volatile("cp.async.commit_group;" ::: "memory")
#define CP_WAIT1()  asm volatile("cp.async.wait_group 1;" ::: "memory")
#define CP_WAIT0()  asm volatile("cp.async.wait_group 0;" ::: "memory")

__device__ __forceinline__ void ldsm4(uint32_t& r0, uint32_t& r1, uint32_t& r2, uint32_t& r3,
                                      uint32_t a) {
    asm volatile("ldmatrix.sync.aligned.m8n8.x4.shared.b16 {%0,%1,%2,%3}, [%4];"
                 : "=r"(r0), "=r"(r1), "=r"(r2), "=r"(r3) : "r"(a));
}
__device__ __forceinline__ void mma16816(float* c, const uint32_t* a, const uint32_t* b) {
    asm volatile("mma.sync.aligned.m16n8k16.row.col.f32.bf16.bf16.f32 "
                 "{%0,%1,%2,%3},{%4,%5,%6,%7},{%8,%9},{%0,%1,%2,%3};"
                 : "+f"(c[0]), "+f"(c[1]), "+f"(c[2]), "+f"(c[3])
                 : "r"(a[0]), "r"(a[1]), "r"(a[2]), "r"(a[3]), "r"(b[0]), "r"(b[1]));
}
#define SWZ(x) ((x) ^ (((x) >> 3) & 0x70))

// ---------------- tensor GEMM: C[M,N] = epi( A[M,K] @ Bt[N,K]^T ) ----------------
// bf16 hi/lo split (AhBh + AhBl + AlBh), fp32 accum. BM=64, BN=64, BK=64,
// SW128 smem, 3 cp.async stages, 2 CTAs/SM. Product-major MMA order for ILP.
#define MT 2
#define BMc 64
#define A_HALF (BMc * 128)
#define B_HALF (64 * 128)
#define STAGE (2 * A_HALF + 2 * B_HALF)
#define SMEMB (3 * STAGE)

__global__ __launch_bounds__(256, 2) void tgemm(
    const bf* __restrict__ Ah, const bf* __restrict__ Al,
    const bf* __restrict__ Bh, const bf* __restrict__ Bl,
    float* __restrict__ Cf, bf* __restrict__ Ch, bf* __restrict__ Cl,
    long Crs, long Ccs,
    int Md, int Nd, int Kd,
    int epi, const float* __restrict__ e0, const float* __restrict__ e1,
    const float* __restrict__ e2, float* __restrict__ o1)
{
    extern __shared__ char sm[];
    const uint32_t sbase = smem_u32(sm);
    const int tid = threadIdx.x;
    const int wid = tid >> 5, lane = tid & 31;
    const int wm = wid >> 2, wn = wid & 3;
    const int i0 = blockIdx.y * BMc, j0 = blockIdx.x * 64;
    const int nch = (Kd + 63) >> 6;

    auto fill = [&](int c) {
        const uint32_t st = sbase + (c % 3) * STAGE;
        const int k0 = c << 6;
        // A: 2 mats * 64 rows * 8 segs of 16B = 1024 cp
#pragma unroll
        for (int t = 0; t < 4; t++) {
            int idx = tid + t * 256;
            int seg = idx & 7, r = (idx >> 3) & (BMc - 1);
            int mat = idx >> 9;
            int gi = i0 + r, gk = k0 + seg * 8;
            bool ok = (gi < Md) && (gk < Kd);
            const bf* src = (mat ? Al : Ah) + (long)gi * Kd + gk;
            cp16(st + mat * A_HALF + SWZ((uint32_t)(r * 128 + seg * 16)),
                 ok ? (const void*)src : (const void*)Ah, ok ? 16 : 0);
        }
        // B: 2 mats * 64 rows * 8 segs = 1024 cp
#pragma unroll
        for (int t = 0; t < 4; t++) {
            int idx = tid + t * 256;
            int seg = idx & 7, r = (idx >> 3) & 63;
            int mat = idx >> 9;
            int gj = j0 + r, gk = k0 + seg * 8;
            bool ok = (gj < Nd) && (gk < Kd);
            const bf* src = (mat ? Bl : Bh) + (long)gj * Kd + gk;
            cp16(st + 2 * A_HALF + mat * B_HALF + SWZ((uint32_t)(r * 128 + seg * 16)),
                 ok ? (const void*)src : (const void*)Bh, ok ? 16 : 0);
        }
    };

    float acc[MT][2][4];
#pragma unroll
    for (int a = 0; a < MT; a++)
#pragma unroll
        for (int b = 0; b < 2; b++)
#pragma unroll
            for (int r = 0; r < 4; r++) acc[a][b][r] = 0.f;

    const uint32_t arow = (uint32_t)((wm * (BMc / 2) + (lane & 15)) * 128 + (lane >> 4) * 16);
    const uint32_t brow = (uint32_t)((wn * 16 + (lane & 15)) * 128 + (lane >> 4) * 16);

    fill(0); CP_COMMIT();
    if (nch > 1) fill(1);
    CP_COMMIT();

    for (int c = 0; c < nch; c++) {
        CP_WAIT1();
        __syncthreads();
        if (c + 2 < nch) fill(c + 2);
        CP_COMMIT();

        const uint32_t st = sbase + (c % 3) * STAGE;
#pragma unroll
        for (int ks = 0; ks < 4; ks++) {
            uint32_t bh_[2][2], bl_[2][2], ah_[MT][4], al_[MT][4];
            {
                uint32_t r0, r1, r2, r3;
                ldsm4(r0, r1, r2, r3, st + 2 * A_HALF + SWZ(brow + ks * 32));
                bh_[0][0] = r0; bh_[0][1] = r2; bh_[1][0] = r1; bh_[1][1] = r3;
                ldsm4(r0, r1, r2, r3, st + 2 * A_HALF + B_HALF + SWZ(brow + ks * 32));
                bl_[0][0] = r0; bl_[0][1] = r2; bl_[1][0] = r1; bl_[1][1] = r3;
            }
#pragma unroll
            for (int mt = 0; mt < MT; mt++) {
                ldsm4(ah_[mt][0], ah_[mt][1], ah_[mt][2], ah_[mt][3],
                      st + SWZ(arow + mt * 16 * 128 + ks * 32));
                ldsm4(al_[mt][0], al_[mt][1], al_[mt][2], al_[mt][3],
                      st + A_HALF + SWZ(arow + mt * 16 * 128 + ks * 32));
            }
            // product-major: acc reuse distance = MT*2 independent MMAs
#pragma unroll
            for (int mt = 0; mt < MT; mt++)
#pragma unroll
                for (int nt = 0; nt < 2; nt++)
                    mma16816(acc[mt][nt], ah_[mt], bh_[nt]);
#pragma unroll
            for (int mt = 0; mt < MT; mt++)
#pragma unroll
                for (int nt = 0; nt < 2; nt++)
                    mma16816(acc[mt][nt], ah_[mt], bl_[nt]);
#pragma unroll
            for (int mt = 0; mt < MT; mt++)
#pragma unroll
                for (int nt = 0; nt < 2; nt++)
                    mma16816(acc[mt][nt], al_[mt], bh_[nt]);
        }
    }

    // ---------------- epilogue ----------------
    const int rbase = i0 + wm * (BMc / 2) + (lane >> 2);
    const int cb = j0 + wn * 16 + (lane & 3) * 2;
#pragma unroll
    for (int mt = 0; mt < MT; mt++) {
#pragma unroll
        for (int nt = 0; nt < 2; nt++) {
#pragma unroll
            for (int rr = 0; rr < 2; rr++) {
#pragma unroll
                for (int cc = 0; cc < 2; cc++) {
                    int i = rbase + mt * 16 + rr * 8;
                    int j = cb + nt * 8 + cc;
                    if (i >= Md || j >= Nd) continue;
                    float v = acc[mt][nt][rr * 2 + cc];
                    long rm = (long)i * Nd + j;
                    float out;
                    switch (epi) {
                        default:
                        case 0: out = v; break;
                        case 1: out = fmaxf(v + e0[j], 0.f); break;
                        case 2: out = tanhf(v + e0[j]) * e1[j & 7]; break;
                        case 3: out = v + e0[j]; break;
                        case 4: out = fminf(v, e0[rm]); break;
                        case 5: {
                            float s = v + e0[rm] + e1[rm];
                            float yn = fmaxf(s - e2[rm], 0.f);
                            o1[rm] = yn;
                            out = s - 2.f * yn;
                        } break;
                        case 6: out = 2.f * v; break;
                        case 7: out = (i == j) ? v + 2.f : v; break;
                        case 8: out = 2.f * e0[rm] - v; break;
                        case 9: out = v + e0[rm]; break;
                    }
                    if (Cf) Cf[(long)i * Crs + (long)j * Ccs] = out;
                    if (Ch) {
                        bf h16 = __float2bfloat16(out);
                        Ch[rm] = h16;
                        Cl[rm] = __float2bfloat16(out - __bfloat162float(h16));
                    }
                }
            }
        }
    }
    CP_WAIT0();
}

// ---------------- fused prep kernel ----------------
__device__ __forceinline__ void split_one(float x, bf* h, bf* l, long o) {
    bf b = __float2bfloat16(x);
    h[o] = b;
    l[o] = __float2bfloat16(x - __bfloat162float(b));
}
__global__ void prep_all(const float* __restrict__ X0, const float* __restrict__ W1,
                         const float* __restrict__ W2, const float* __restrict__ W3,
                         const float* __restrict__ H0, const float* __restrict__ F,
                         bf* x0th, bf* x0tl, bf* w1th, bf* w1tl, bf* w2th, bf* w2tl,
                         bf* w3th, bf* w3tl, bf* h0h, bf* h0l, bf* fh, bf* fl,
                         bf* fth, bf* ftl)
{
    long idx = (long)blockIdx.x * blockDim.x + threadIdx.x;
    const long n0 = NN * NB, n1 = NN * HIDD, n2 = HIDD * HIDD, n3 = HIDD * DD;
    const long n4 = NC * NN, n5 = (long)NC * DD, n6 = (long)NC * DD;
    if (idx < n0) {
        int r = idx / NB, c = idx - (long)r * NB;
        split_one(X0[idx], x0th, x0tl, (long)c * NN + r);
        return;
    }
    idx -= n0;
    if (idx < n1) {
        int r = idx / HIDD, c = idx - (long)r * HIDD;
        split_one(W1[idx], w1th, w1tl, (long)c * NN + r);
        return;
    }
    idx -= n1;
    if (idx < n2) {
        int r = idx / HIDD, c = idx - (long)r * HIDD;
        split_one(W2[idx], w2th, w2tl, (long)c * HIDD + r);
        return;
    }
    idx -= n2;
    if (idx < n3) {
        int r = idx / DD, c = idx - (long)r * DD;
        split_one(W3[idx], w3th, w3tl, (long)c * HIDD + r);
        return;
    }
    idx -= n3;
    if (idx < n4) { split_one(H0[idx], h0h, h0l, idx); return; }
    idx -= n4;
    if (idx < n5) { split_one(F[idx], fh, fl, idx); return; }
    idx -= n5;
    if (idx < n6) {
        int r = idx / DD, c = idx - (long)r * DD;
        split_one(F[idx], fth, ftl, (long)c * NC + r);
        return;
    }
}

// ---------------- small kernels ----------------
__global__ void transpose_split(const float* __restrict__ s, bf* __restrict__ h,
                                bf* __restrict__ l, int R, int C) {
    long i = (long)blockIdx.x * blockDim.x + threadIdx.x;
    if (i < (long)R * C) {
        int r = i / C, c = i - (long)r * C;
        split_one(s[i], h, l, (long)c * R + r);
    }
}
__global__ void gershgorin_kernel(const float* __restrict__ K, int n) {
    __shared__ float red[512];
    float mx = 0.f;
    for (int i = threadIdx.x; i < n; i += blockDim.x) {
        float sum = 0.f;
        for (int j = 0; j < n; j++) sum += fabsf(K[i * n + j]);
        mx = fmaxf(mx, sum);
    }
    red[threadIdx.x] = mx;
    __syncthreads();
    for (int s = 256; s > 0; s >>= 1) {
        if (threadIdx.x < s) red[threadIdx.x] = fmaxf(red[threadIdx.x], red[threadIdx.x + s]);
        __syncthreads();
    }
    if (threadIdx.x == 0) g_alpha = 2.f / (2.f + red[0]);
}
__global__ void init_diag_split(float* __restrict__ Xf, bf* __restrict__ Xh,
                                bf* __restrict__ Xl, int n) {
    int idx = blockIdx.x * blockDim.x + threadIdx.x;
    if (idx < n * n) {
        int i = idx / n, j = idx - i * n;
        float v = (i == j) ? g_alpha : 0.f;
        Xf[idx] = v;
        bf b = __float2bfloat16(v);
        Xh[idx] = b;
        Xl[idx] = __float2bfloat16(v - __bfloat162float(b));
    }
}
__global__ void zero_kernel(float* __restrict__ p, int n) {
    int i = blockIdx.x * blockDim.x + threadIdx.x;
    if (i < n) p[i] = 0.f;
}

// ---------------- host ----------------
static inline void tg(const bf* Ah, const bf* Al, const bf* Bh, const bf* Bl,
                      float* Cf, bf* Ch, bf* Cl, long Crs, long Ccs,
                      int M, int N, int K, int epi,
                      const float* e0 = nullptr, const float* e1 = nullptr,
                      const float* e2 = nullptr, float* o1 = nullptr)
{
    dim3 grid((N + 63) / 64, (M + BMc - 1) / BMc);
    tgemm<<<grid, 256, SMEMB>>>(Ah, Al, Bh, Bl, Cf, Ch, Cl, Crs, Ccs,
                                M, N, K, epi, e0, e1, e2, o1);
}

template <typename T> static inline T* sym(const void* s) {
    void* p = nullptr;
    cudaGetSymbolAddress(&p, s);
    return (T*)p;
}

extern "C" void kernel_launch(void* const* d_in, const int* in_sizes, int n_in,
                              void* d_out, int out_size)
{
    const float* X0   = (const float*)d_in[0];
    const float* W1   = (const float*)d_in[1];
    const float* b1   = (const float*)d_in[2];
    const float* W2   = (const float*)d_in[3];
    const float* b2   = (const float*)d_in[4];
    const float* W3   = (const float*)d_in[5];
    const float* b3   = (const float*)d_in[6];
    const float* ubar = (const float*)d_in[7];
    const float* F    = (const float*)d_in[8];
    const float* gg   = (const float*)d_in[9];
    const float* H0   = (const float*)d_in[10];
    float* out = (float*)d_out;

    cudaFuncSetAttribute(tgemm, cudaFuncAttributeMaxDynamicSharedMemorySize, SMEMB);

    float *pKf = sym<float>(dKf), *pXaf = sym<float>(dXaf), *pXbf = sym<float>(dXbf);
    float *pFKf = sym<float>(dFKf), *pCf = sym<float>(dCf_), *pbf = sym<float>(dbf_);
    float *pyf = sym<float>(dyf_), *pUf = sym<float>(dUf_);

    bf *x0th = sym<bf>(X0Th), *x0tl = sym<bf>(X0Tl);
    bf *w1th = sym<bf>(W1Th), *w1tl = sym<bf>(W1Tl);
    bf *w2th = sym<bf>(W2Th), *w2tl = sym<bf>(W2Tl);
    bf *w3th = sym<bf>(W3Th), *w3tl = sym<bf>(W3Tl);
    bf *h0h = sym<bf>(H0h_), *h0l = sym<bf>(H0l_);
    bf *fh = sym<bf>(Fh_), *fl = sym<bf>(Fl_);
    bf *fth = sym<bf>(FTh_), *ftl = sym<bf>(FTl_);
    bf *h1h = sym<bf>(H1h_), *h1l = sym<bf>(H1l_);
    bf *h2h = sym<bf>(H2h_), *h2l = sym<bf>(H2l_);
    bf *vh = sym<bf>(Vh_), *vl = sym<bf>(Vl_);
    bf *kh = sym<bf>(Kh_), *kl = sym<bf>(Kl_);
    bf *xah = sym<bf>(Xah_), *xal = sym<bf>(Xal_);
    bf *xbh = sym<bf>(Xbh_), *xbl = sym<bf>(Xbl_);
    bf *yh = sym<bf>(Yh_), *yl = sym<bf>(Yl_);
    bf *fkh = sym<bf>(FKh_), *fkl = sym<bf>(FKl_);
    bf *fkth = sym<bf>(FKTh_), *fktl = sym<bf>(FKTl_);
    bf *ghh = sym<bf>(Gh_), *gll = sym<bf>(Gl_);
    bf *wah = sym<bf>(Wah_), *wal = sym<bf>(Wal_);
    bf *wbh = sym<bf>(Wbh_), *wbl = sym<bf>(Wbl_);

    // fused prep
    {
        long total = (long)NN*NB + (long)NN*HIDD + (long)HIDD*HIDD + (long)HIDD*DD
                   + (long)NC*NN + (long)NC*DD + (long)NC*DD;
        prep_all<<<(int)((total + 255) / 256), 256>>>(
            X0, W1, W2, W3, H0, F,
            x0th, x0tl, w1th, w1tl, w2th, w2tl, w3th, w3tl,
            h0h, h0l, fh, fl, fth, ftl);
    }

    // MLP head
    tg(x0th, x0tl, w1th, w1tl, nullptr, h1h, h1l, HIDD, 1, NB, HIDD, NN, 1, b1);
    tg(h1h, h1l, w2th, w2tl, nullptr, h2h, h2l, HIDD, 1, NB, HIDD, HIDD, 1, b2);
    tg(h2h, h2l, w3th, w3tl, nullptr, vh, vl, DD, 1, NB, DD, HIDD, 2, b3, ubar);

    // b = g + X0^T H0^T
    tg(x0th, x0tl, h0h, h0l, pbf, nullptr, nullptr, NC, 1, NB, NC, NN, 3, gg);

    // K = 2I + F^T F
    tg(fth, ftl, fth, ftl, pKf, kh, kl, DD, 1, DD, DD, NC, 7);

    // Kinv: Newton-Schulz
    gershgorin_kernel<<<1, 512>>>(pKf, DD);
    init_diag_split<<<(DD*DD + 255)/256, 256>>>(pXaf, xah, xal, DD);
    {
        float *Xcf = pXaf, *Xnf = pXbf;
        bf *Xch = xah, *Xcl = xal, *Xnh = xbh, *Xnl = xbl;
        for (int t = 0; t < NEWTON_ITERS; t++) {
            tg(Xch, Xcl, kh, kl, nullptr, yh, yl, DD, 1, DD, DD, DD, 0);
            tg(yh, yl, Xch, Xcl, Xnf, Xnh, Xnl, DD, 1, DD, DD, DD, 8, Xcf);
            float* tf = Xcf; Xcf = Xnf; Xnf = tf;
            bf* t1 = Xch; Xch = Xnh; Xnh = t1;
            bf* t2 = Xcl; Xcl = Xnl; Xnl = t2;
        }
    }

    // precompute: FK, FKT, G, C
    tg(fh, fl, xah, xal, pFKf, fkh, fkl, DD, 1, NC, DD, DD, 0);
    transpose_split<<<(NC*DD + 255)/256, 256>>>(pFKf, fkth, fktl, NC, DD);
    tg(fkh, fkl, fh, fl, nullptr, ghh, gll, NC, 1, NC, NC, DD, 0);
    tg(vh, vl, fkh, fkl, pCf, nullptr, nullptr, NC, 1, NB, NC, DD, 6);

    // init: w0 = min(V F^T, b), y = 0
    tg(vh, vl, fh, fl, nullptr, wah, wal, NC, 1, NB, NC, DD, 4, pbf);
    zero_kernel<<<(NB*NC + 255)/256, 256>>>(pyf, NB * NC);

    // ADMM: s = C + y + w G ; y = max(s-b,0) ; w = s - 2y
    {
        bf *wch = wah, *wcl = wal, *wnh = wbh, *wnl = wbl;
        for (int t = 0; t < ADMM_ITERS; t++) {
            tg(wch, wcl, ghh, gll, nullptr, wnh, wnl, NC, 1,
               NB, NC, NC, 5, pCf, pyf, pbf, pyf);
            bf* t1 = wch; wch = wnh; wnh = t1;
            bf* t2 = wcl; wcl = wnl; wnl = t2;
        }
    }

    // u = 2 V Kinv + w FK ; out = u^T
    tg(vh, vl, xah, xal, pUf, nullptr, nullptr, DD, 1, NB, DD, DD, 6);
    tg(wah, wal, fkth, fktl, out, nullptr, nullptr, 1, NB, NB, DD, NC, 9, pUf);
}

// round 12
// speedup vs baseline: 2.8657x; 1.1988x over previous
#include <cuda_runtime.h>
#include <cuda_bf16.h>
#include <math.h>
#include <stdint.h>

#define NB   1024
#define NN   32
#define HIDD 512
#define DD   400
#define NC   800
#define ADMM_ITERS 40
#define NEWTON_ITERS 8
#define NCH_ADMM 13           // ceil(800/64)
#define ADMM_GRID_X 13
#define ADMM_GRID_Y 16
#define ADMM_NBLOCKS (ADMM_GRID_X * ADMM_GRID_Y)

typedef __nv_bfloat16 bf;

// ---------------- device scratch ----------------
__device__ float g_alpha;
__device__ unsigned g_cnt, g_gen;
__device__ float dKf[DD*DD];
__device__ float dXaf[DD*DD], dXbf[DD*DD];
__device__ float dFKf[NC*DD];
__device__ float dCf_[NB*NC];
__device__ float dbf_[NB*NC];
__device__ float dyf_[NB*NC];
__device__ float dUf_[NB*DD];

__device__ bf X0Th[NB*NN], X0Tl[NB*NN];
__device__ bf W1Th[HIDD*NN], W1Tl[HIDD*NN];
__device__ bf W2Th[HIDD*HIDD], W2Tl[HIDD*HIDD];
__device__ bf W3Th[DD*HIDD], W3Tl[DD*HIDD];
__device__ bf H0h_[NC*NN], H0l_[NC*NN];
__device__ bf Fh_[NC*DD], Fl_[NC*DD];
__device__ bf FTh_[DD*NC], FTl_[DD*NC];
__device__ bf H1h_[NB*HIDD], H1l_[NB*HIDD];
__device__ bf H2h_[NB*HIDD], H2l_[NB*HIDD];
__device__ bf Vh_[NB*DD], Vl_[NB*DD];
__device__ bf Kh_[DD*DD], Kl_[DD*DD];
__device__ bf Xah_[DD*DD], Xal_[DD*DD];
__device__ bf Xbh_[DD*DD], Xbl_[DD*DD];
__device__ bf Yh_[DD*DD], Yl_[DD*DD];
__device__ bf FKh_[NC*DD], FKl_[NC*DD];
__device__ bf FKTh_[DD*NC], FKTl_[DD*NC];
__device__ bf Gh_[NC*NC], Gl_[NC*NC];
__device__ bf Wah_[NB*NC], Wal_[NB*NC];
__device__ bf Wbh_[NB*NC], Wbl_[NB*NC];

// ---------------- PTX helpers ----------------
__device__ __forceinline__ uint32_t smem_u32(const void* p) {
    uint32_t a;
    asm("{ .reg .u64 t; cvta.to.shared.u64 t, %1; cvt.u32.u64 %0, t; }" : "=r"(a) : "l"(p));
    return a;
}
__device__ __forceinline__ void cp16(uint32_t sa, const void* g, int bytes) {
    asm volatile("cp.async.cg.shared.global [%0], [%1], 16, %2;"
                 :: "r"(sa), "l"(g), "r"(bytes) : "memory");
}
#define CP_COMMIT() asm volatile("cp.async.commit_group;" ::: "memory")
#define CP_WAIT1()  asm volatile("cp.async.wait_group 1;" ::: "memory")
#define CP_WAIT0()  asm volatile("cp.async.wait_group 0;" ::: "memory")

__device__ __forceinline__ void ldsm4(uint32_t* r, uint32_t a) {
    asm volatile("ldmatrix.sync.aligned.m8n8.x4.shared.b16 {%0,%1,%2,%3}, [%4];"
                 : "=r"(r[0]), "=r"(r[1]), "=r"(r[2]), "=r"(r[3]) : "r"(a));
}
__device__ __forceinline__ void mma2(float* c, uint32_t a0, uint32_t a1, uint32_t a2,
                                     uint32_t a3, uint32_t b0, uint32_t b1) {
    asm volatile("mma.sync.aligned.m16n8k16.row.col.f32.bf16.bf16.f32 "
                 "{%0,%1,%2,%3},{%4,%5,%6,%7},{%8,%9},{%0,%1,%2,%3};"
                 : "+f"(c[0]), "+f"(c[1]), "+f"(c[2]), "+f"(c[3])
                 : "r"(a0), "r"(a1), "r"(a2), "r"(a3), "r"(b0), "r"(b1));
}
#define SWZ(x) ((x) ^ (((x) >> 3) & 0x70))

// shared tile geometry (BM=BN=64, BK=64)
#define A_HALF (64 * 128)
#define B_HALF (64 * 128)
#define STAGE (2 * A_HALF + 2 * B_HALF)
#define SMEMB (3 * STAGE)

// ---------------- generic tensor GEMM (unchanged from R10, passing) ----------------
__global__ __launch_bounds__(256, 2) void tgemm(
    const bf* __restrict__ Ah, const bf* __restrict__ Al,
    const bf* __restrict__ Bh, const bf* __restrict__ Bl,
    float* __restrict__ Cf, bf* __restrict__ Ch, bf* __restrict__ Cl,
    long Crs, long Ccs,
    int Md, int Nd, int Kd,
    int epi, const float* __restrict__ e0, const float* __restrict__ e1,
    const float* __restrict__ e2, float* __restrict__ o1)
{
    extern __shared__ char sm[];
    const uint32_t sbase = smem_u32(sm);
    const int tid = threadIdx.x;
    const int wid = tid >> 5, lane = tid & 31;
    const int wm = wid >> 2, wn = wid & 3;
    const int i0 = blockIdx.y * 64, j0 = blockIdx.x * 64;
    const int nch = (Kd + 63) >> 6;

    auto fill = [&](int c) {
        const uint32_t st = sbase + (c % 3) * STAGE;
        const int k0 = c << 6;
#pragma unroll
        for (int t = 0; t < 4; t++) {
            int idx = tid + t * 256;
            int seg = idx & 7, r = (idx >> 3) & 63;
            int mat = idx >> 9;
            int gi = i0 + r, gk = k0 + seg * 8;
            bool ok = (gi < Md) && (gk < Kd);
            const bf* src = (mat ? Al : Ah) + (long)gi * Kd + gk;
            cp16(st + mat * A_HALF + SWZ((uint32_t)(r * 128 + seg * 16)),
                 ok ? (const void*)src : (const void*)Ah, ok ? 16 : 0);
        }
#pragma unroll
        for (int t = 0; t < 4; t++) {
            int idx = tid + t * 256;
            int seg = idx & 7, r = (idx >> 3) & 63;
            int mat = idx >> 9;
            int gj = j0 + r, gk = k0 + seg * 8;
            bool ok = (gj < Nd) && (gk < Kd);
            const bf* src = (mat ? Bl : Bh) + (long)gj * Kd + gk;
            cp16(st + 2 * A_HALF + mat * B_HALF + SWZ((uint32_t)(r * 128 + seg * 16)),
                 ok ? (const void*)src : (const void*)Bh, ok ? 16 : 0);
        }
    };

    float acc[2][2][4];
#pragma unroll
    for (int a = 0; a < 2; a++)
#pragma unroll
        for (int b = 0; b < 2; b++)
#pragma unroll
            for (int r = 0; r < 4; r++) acc[a][b][r] = 0.f;

    const uint32_t arow = (uint32_t)((wm * 32 + (lane & 15)) * 128 + (lane >> 4) * 16);
    const uint32_t brow = (uint32_t)((wn * 16 + (lane & 15)) * 128 + (lane >> 4) * 16);

    fill(0); CP_COMMIT();
    if (nch > 1) fill(1);
    CP_COMMIT();

    for (int c = 0; c < nch; c++) {
        CP_WAIT1();
        __syncthreads();
        if (c + 2 < nch) fill(c + 2);
        CP_COMMIT();

        const uint32_t st = sbase + (c % 3) * STAGE;
#pragma unroll
        for (int ks = 0; ks < 4; ks++) {
            uint32_t bh_[4], bl_[4], ah_[2][4], al_[2][4];
            ldsm4(bh_, st + 2 * A_HALF + SWZ(brow + ks * 32));
            ldsm4(bl_, st + 2 * A_HALF + B_HALF + SWZ(brow + ks * 32));
#pragma unroll
            for (int mt = 0; mt < 2; mt++) {
                ldsm4(ah_[mt], st + SWZ(arow + mt * 16 * 128 + ks * 32));
                ldsm4(al_[mt], st + A_HALF + SWZ(arow + mt * 16 * 128 + ks * 32));
            }
#pragma unroll
            for (int mt = 0; mt < 2; mt++) {
                mma2(acc[mt][0], ah_[mt][0], ah_[mt][1], ah_[mt][2], ah_[mt][3], bh_[0], bh_[2]);
                mma2(acc[mt][1], ah_[mt][0], ah_[mt][1], ah_[mt][2], ah_[mt][3], bh_[1], bh_[3]);
            }
#pragma unroll
            for (int mt = 0; mt < 2; mt++) {
                mma2(acc[mt][0], ah_[mt][0], ah_[mt][1], ah_[mt][2], ah_[mt][3], bl_[0], bl_[2]);
                mma2(acc[mt][1], ah_[mt][0], ah_[mt][1], ah_[mt][2], ah_[mt][3], bl_[1], bl_[3]);
            }
#pragma unroll
            for (int mt = 0; mt < 2; mt++) {
                mma2(acc[mt][0], al_[mt][0], al_[mt][1], al_[mt][2], al_[mt][3], bh_[0], bh_[2]);
                mma2(acc[mt][1], al_[mt][0], al_[mt][1], al_[mt][2], al_[mt][3], bh_[1], bh_[3]);
            }
        }
    }

    const int rbase = i0 + wm * 32 + (lane >> 2);
    const int cb = j0 + wn * 16 + (lane & 3) * 2;
#pragma unroll
    for (int mt = 0; mt < 2; mt++) {
#pragma unroll
        for (int nt = 0; nt < 2; nt++) {
#pragma unroll
            for (int rr = 0; rr < 2; rr++) {
#pragma unroll
                for (int cc = 0; cc < 2; cc++) {
                    int i = rbase + mt * 16 + rr * 8;
                    int j = cb + nt * 8 + cc;
                    if (i >= Md || j >= Nd) continue;
                    float v = acc[mt][nt][rr * 2 + cc];
                    long rm = (long)i * Nd + j;
                    float out;
                    switch (epi) {
                        default:
                        case 0: out = v; break;
                        case 1: out = fmaxf(v + e0[j], 0.f); break;
                        case 2: out = tanhf(v + e0[j]) * e1[j & 7]; break;
                        case 3: out = v + e0[j]; break;
                        case 4: out = fminf(v, e0[rm]); break;
                        case 6: out = 2.f * v; break;
                        case 7: out = (i == j) ? v + 2.f : v; break;
                        case 8: out = 2.f * e0[rm] - v; break;
                        case 9: out = v + e0[rm]; break;
                    }
                    if (Cf) Cf[(long)i * Crs + (long)j * Ccs] = out;
                    if (Ch) {
                        bf h16 = __float2bfloat16(out);
                        Ch[rm] = h16;
                        Cl[rm] = __float2bfloat16(out - __bfloat162float(h16));
                    }
                }
            }
        }
    }
    CP_WAIT0();
}

// ---------------- persistent ADMM kernel ----------------
__device__ __forceinline__ void grid_barrier(unsigned target) {
    __threadfence();
    __syncthreads();
    if (threadIdx.x == 0) {
        unsigned t = atomicAdd(&g_cnt, 1u);
        if (t == (unsigned)(ADMM_NBLOCKS - 1)) {
            g_cnt = 0u;
            __threadfence();
            atomicAdd(&g_gen, 1u);
        } else {
            while (atomicAdd(&g_gen, 0u) < target) { }
        }
    }
    __syncthreads();
}

__global__ __launch_bounds__(256, 2) void admm_persist(
    const bf* __restrict__ Gh, const bf* __restrict__ Gl,
    const float* __restrict__ Cf, const float* __restrict__ bfv,
    float* __restrict__ yf,
    bf* __restrict__ wah, bf* __restrict__ wal,
    bf* __restrict__ wbh, bf* __restrict__ wbl)
{
    extern __shared__ char sm[];
    const uint32_t sbase = smem_u32(sm);
    const int tid = threadIdx.x;
    const int wid = tid >> 5, lane = tid & 31;
    const int wm = wid >> 2, wn = wid & 3;
    const int i0 = blockIdx.y * 64, j0 = blockIdx.x * 64;

    const uint32_t arow = (uint32_t)((wm * 32 + (lane & 15)) * 128 + (lane >> 4) * 16);
    const uint32_t brow = (uint32_t)((wn * 16 + (lane & 15)) * 128 + (lane >> 4) * 16);

    // epilogue coords
    const int rbase = i0 + wm * 32 + (lane >> 2);
    const int cb = j0 + wn * 16 + (lane & 3) * 2;

    for (int t = 0; t < ADMM_ITERS; t++) {
        const bf* Ah = (t & 1) ? wbh : wah;
        const bf* Al = (t & 1) ? wbl : wal;
        bf* Oh = (t & 1) ? wah : wbh;
        bf* Ol = (t & 1) ? wal : wbl;

        auto fill = [&](int c) {
            const uint32_t st = sbase + (c % 3) * STAGE;
            const int k0 = c << 6;
#pragma unroll
            for (int it = 0; it < 4; it++) {
                int idx = tid + it * 256;
                int seg = idx & 7, r = (idx >> 3) & 63;
                int mat = idx >> 9;
                int gi = i0 + r, gk = k0 + seg * 8;
                bool ok = gk < NC;
                const bf* src = (mat ? Al : Ah) + (long)gi * NC + gk;
                cp16(st + mat * A_HALF + SWZ((uint32_t)(r * 128 + seg * 16)),
                     ok ? (const void*)src : (const void*)Ah, ok ? 16 : 0);
            }
#pragma unroll
            for (int it = 0; it < 4; it++) {
                int idx = tid + it * 256;
                int seg = idx & 7, r = (idx >> 3) & 63;
                int mat = idx >> 9;
                int gj = j0 + r, gk = k0 + seg * 8;
                bool ok = (gj < NC) && (gk < NC);
                const bf* src = (mat ? Gl : Gh) + (long)gj * NC + gk;
                cp16(st + 2 * A_HALF + mat * B_HALF + SWZ((uint32_t)(r * 128 + seg * 16)),
                     ok ? (const void*)src : (const void*)Gh, ok ? 16 : 0);
            }
        };

        float acc[2][2][4];
#pragma unroll
        for (int a = 0; a < 2; a++)
#pragma unroll
            for (int b = 0; b < 2; b++)
#pragma unroll
                for (int r = 0; r < 4; r++) acc[a][b][r] = 0.f;

        fill(0); CP_COMMIT();
        fill(1); CP_COMMIT();

        uint32_t ah_[2][2][4], al_[2][2][4], bh_[2][4], bl_[2][4];

        for (int c = 0; c < NCH_ADMM; c++) {
            CP_WAIT1();
            __syncthreads();
            if (c + 2 < NCH_ADMM) fill(c + 2);
            CP_COMMIT();

            const uint32_t st = sbase + (c % 3) * STAGE;
            // preload ks=0 frags into buf 0
            ldsm4(bh_[0], st + 2 * A_HALF + SWZ(brow));
            ldsm4(bl_[0], st + 2 * A_HALF + B_HALF + SWZ(brow));
#pragma unroll
            for (int mt = 0; mt < 2; mt++) {
                ldsm4(ah_[0][mt], st + SWZ(arow + mt * 2048));
                ldsm4(al_[0][mt], st + A_HALF + SWZ(arow + mt * 2048));
            }
#pragma unroll
            for (int ks = 0; ks < 4; ks++) {
                const int cur = ks & 1, nxt = cur ^ 1;
                if (ks < 3) {
                    ldsm4(bh_[nxt], st + 2 * A_HALF + SWZ(brow + (ks + 1) * 32));
                    ldsm4(bl_[nxt], st + 2 * A_HALF + B_HALF + SWZ(brow + (ks + 1) * 32));
#pragma unroll
                    for (int mt = 0; mt < 2; mt++) {
                        ldsm4(ah_[nxt][mt], st + SWZ(arow + mt * 2048 + (ks + 1) * 32));
                        ldsm4(al_[nxt][mt], st + A_HALF + SWZ(arow + mt * 2048 + (ks + 1) * 32));
                    }
                }
#pragma unroll
                for (int mt = 0; mt < 2; mt++) {
                    mma2(acc[mt][0], ah_[cur][mt][0], ah_[cur][mt][1], ah_[cur][mt][2],
                         ah_[cur][mt][3], bh_[cur][0], bh_[cur][2]);
                    mma2(acc[mt][1], ah_[cur][mt][0], ah_[cur][mt][1], ah_[cur][mt][2],
                         ah_[cur][mt][3], bh_[cur][1], bh_[cur][3]);
                }
#pragma unroll
                for (int mt = 0; mt < 2; mt++) {
                    mma2(acc[mt][0], ah_[cur][mt][0], ah_[cur][mt][1], ah_[cur][mt][2],
                         ah_[cur][mt][3], bl_[cur][0], bl_[cur][2]);
                    mma2(acc[mt][1], ah_[cur][mt][0], ah_[cur][mt][1], ah_[cur][mt][2],
                         ah_[cur][mt][3], bl_[cur][1], bl_[cur][3]);
                }
#pragma unroll
                for (int mt = 0; mt < 2; mt++) {
                    mma2(acc[mt][0], al_[cur][mt][0], al_[cur][mt][1], al_[cur][mt][2],
                         al_[cur][mt][3], bh_[cur][0], bh_[cur][2]);
                    mma2(acc[mt][1], al_[cur][mt][0], al_[cur][mt][1], al_[cur][mt][2],
                         al_[cur][mt][3], bh_[cur][1], bh_[cur][3]);
                }
            }
        }
        CP_WAIT0();

        // epilogue: s = acc + C + y ; y = max(s-b, 0) ; w = s - 2y (hi/lo split)
#pragma unroll
        for (int mt = 0; mt < 2; mt++) {
#pragma unroll
            for (int nt = 0; nt < 2; nt++) {
#pragma unroll
                for (int rr = 0; rr < 2; rr++) {
                    int i = rbase + mt * 16 + rr * 8;
                    int j = cb + nt * 8;
                    if (j >= NC) continue;
                    long rm = (long)i * NC + j;
                    float2 cf = *(const float2*)&Cf[rm];
                    float2 yv = *(const float2*)&yf[rm];
                    float2 bv = *(const float2*)&bfv[rm];
                    float s0 = acc[mt][nt][rr * 2 + 0] + cf.x + yv.x;
                    float s1 = acc[mt][nt][rr * 2 + 1] + cf.y + yv.y;
                    float yn0 = fmaxf(s0 - bv.x, 0.f);
                    float yn1 = fmaxf(s1 - bv.y, 0.f);
                    float o0 = s0 - 2.f * yn0;
                    float o1v = s1 - 2.f * yn1;
                    *(float2*)&yf[rm] = make_float2(yn0, yn1);
                    bf h0 = __float2bfloat16(o0);
                    bf h1 = __float2bfloat16(o1v);
                    bf l0 = __float2bfloat16(o0 - __bfloat162float(h0));
                    bf l1 = __float2bfloat16(o1v - __bfloat162float(h1));
                    uint32_t ph = ((uint32_t)*(uint16_t*)&h1 << 16) | *(uint16_t*)&h0;
                    uint32_t pl = ((uint32_t)*(uint16_t*)&l1 << 16) | *(uint16_t*)&l0;
                    *(uint32_t*)&Oh[rm] = ph;
                    *(uint32_t*)&Ol[rm] = pl;
                }
            }
        }
        if (t + 1 < ADMM_ITERS) grid_barrier((unsigned)(t + 1));
    }
}

// ---------------- prep / small kernels ----------------
__device__ __forceinline__ void split_one(float x, bf* h, bf* l, long o) {
    bf b = __float2bfloat16(x);
    h[o] = b;
    l[o] = __float2bfloat16(x - __bfloat162float(b));
}
__global__ void prep_all(const float* __restrict__ X0, const float* __restrict__ W1,
                         const float* __restrict__ W2, const float* __restrict__ W3,
                         const float* __restrict__ H0, const float* __restrict__ F,
                         bf* x0th, bf* x0tl, bf* w1th, bf* w1tl, bf* w2th, bf* w2tl,
                         bf* w3th, bf* w3tl, bf* h0h, bf* h0l, bf* fh, bf* fl,
                         bf* fth, bf* ftl, float* yzero)
{
    long idx = (long)blockIdx.x * blockDim.x + threadIdx.x;
    const long n0 = NN * NB, n1 = NN * HIDD, n2 = HIDD * HIDD, n3 = HIDD * DD;
    const long n4 = NC * NN, n5 = (long)NC * DD, n6 = (long)NC * DD;
    const long n7 = (long)NB * NC;
    if (idx < n0) {
        int r = idx / NB, c = idx - (long)r * NB;
        split_one(X0[idx], x0th, x0tl, (long)c * NN + r);
        return;
    }
    idx -= n0;
    if (idx < n1) {
        int r = idx / HIDD, c = idx - (long)r * HIDD;
        split_one(W1[idx], w1th, w1tl, (long)c * NN + r);
        return;
    }
    idx -= n1;
    if (idx < n2) {
        int r = idx / HIDD, c = idx - (long)r * HIDD;
        split_one(W2[idx], w2th, w2tl, (long)c * HIDD + r);
        return;
    }
    idx -= n2;
    if (idx < n3) {
        int r = idx / DD, c = idx - (long)r * DD;
        split_one(W3[idx], w3th, w3tl, (long)c * HIDD + r);
        return;
    }
    idx -= n3;
    if (idx < n4) { split_one(H0[idx], h0h, h0l, idx); return; }
    idx -= n4;
    if (idx < n5) { split_one(F[idx], fh, fl, idx); return; }
    idx -= n5;
    if (idx < n6) {
        int r = idx / DD, c = idx - (long)r * DD;
        split_one(F[idx], fth, ftl, (long)c * NC + r);
        return;
    }
    idx -= n6;
    if (idx < n7) { yzero[idx] = 0.f; return; }
}
__global__ void init_sync() { g_cnt = 0u; g_gen = 0u; }
__global__ void transpose_split(const float* __restrict__ s, bf* __restrict__ h,
                                bf* __restrict__ l, int R, int C) {
    long i = (long)blockIdx.x * blockDim.x + threadIdx.x;
    if (i < (long)R * C) {
        int r = i / C, c = i - (long)r * C;
        split_one(s[i], h, l, (long)c * R + r);
    }
}
__global__ void gershgorin_kernel(const float* __restrict__ K, int n) {
    __shared__ float red[512];
    float mx = 0.f;
    for (int i = threadIdx.x; i < n; i += blockDim.x) {
        float sum = 0.f;
        for (int j = 0; j < n; j++) sum += fabsf(K[i * n + j]);
        mx = fmaxf(mx, sum);
    }
    red[threadIdx.x] = mx;
    __syncthreads();
    for (int s = 256; s > 0; s >>= 1) {
        if (threadIdx.x < s) red[threadIdx.x] = fmaxf(red[threadIdx.x], red[threadIdx.x + s]);
        __syncthreads();
    }
    if (threadIdx.x == 0) g_alpha = 2.f / (2.f + red[0]);
}
__global__ void init_diag_split(float* __restrict__ Xf, bf* __restrict__ Xh,
                                bf* __restrict__ Xl, int n) {
    int idx = blockIdx.x * blockDim.x + threadIdx.x;
    if (idx < n * n) {
        int i = idx / n, j = idx - i * n;
        float v = (i == j) ? g_alpha : 0.f;
        Xf[idx] = v;
        bf b = __float2bfloat16(v);
        Xh[idx] = b;
        Xl[idx] = __float2bfloat16(v - __bfloat162float(b));
    }
}

// ---------------- host ----------------
static inline void tg(const bf* Ah, const bf* Al, const bf* Bh, const bf* Bl,
                      float* Cf, bf* Ch, bf* Cl, long Crs, long Ccs,
                      int M, int N, int K, int epi,
                      const float* e0 = nullptr, const float* e1 = nullptr,
                      const float* e2 = nullptr, float* o1 = nullptr)
{
    dim3 grid((N + 63) / 64, (M + 63) / 64);
    tgemm<<<grid, 256, SMEMB>>>(Ah, Al, Bh, Bl, Cf, Ch, Cl, Crs, Ccs,
                                M, N, K, epi, e0, e1, e2, o1);
}

template <typename T> static inline T* sym(const void* s) {
    void* p = nullptr;
    cudaGetSymbolAddress(&p, s);
    return (T*)p;
}

extern "C" void kernel_launch(void* const* d_in, const int* in_sizes, int n_in,
                              void* d_out, int out_size)
{
    const float* X0   = (const float*)d_in[0];
    const float* W1   = (const float*)d_in[1];
    const float* b1   = (const float*)d_in[2];
    const float* W2   = (const float*)d_in[3];
    const float* b2   = (const float*)d_in[4];
    const float* W3   = (const float*)d_in[5];
    const float* b3   = (const float*)d_in[6];
    const float* ubar = (const float*)d_in[7];
    const float* F    = (const float*)d_in[8];
    const float* gg   = (const float*)d_in[9];
    const float* H0   = (const float*)d_in[10];
    float* out = (float*)d_out;

    cudaFuncSetAttribute(tgemm, cudaFuncAttributeMaxDynamicSharedMemorySize, SMEMB);
    cudaFuncSetAttribute(admm_persist, cudaFuncAttributeMaxDynamicSharedMemorySize, SMEMB);

    float *pKf = sym<float>(dKf), *pXaf = sym<float>(dXaf), *pXbf = sym<float>(dXbf);
    float *pFKf = sym<float>(dFKf), *pCf = sym<float>(dCf_), *pbf = sym<float>(dbf_);
    float *pyf = sym<float>(dyf_), *pUf = sym<float>(dUf_);

    bf *x0th = sym<bf>(X0Th), *x0tl = sym<bf>(X0Tl);
    bf *w1th = sym<bf>(W1Th), *w1tl = sym<bf>(W1Tl);
    bf *w2th = sym<bf>(W2Th), *w2tl = sym<bf>(W2Tl);
    bf *w3th = sym<bf>(W3Th), *w3tl = sym<bf>(W3Tl);
    bf *h0h = sym<bf>(H0h_), *h0l = sym<bf>(H0l_);
    bf *fh = sym<bf>(Fh_), *fl = sym<bf>(Fl_);
    bf *fth = sym<bf>(FTh_), *ftl = sym<bf>(FTl_);
    bf *h1h = sym<bf>(H1h_), *h1l = sym<bf>(H1l_);
    bf *h2h = sym<bf>(H2h_), *h2l = sym<bf>(H2l_);
    bf *vh = sym<bf>(Vh_), *vl = sym<bf>(Vl_);
    bf *kh = sym<bf>(Kh_), *kl = sym<bf>(Kl_);
    bf *xah = sym<bf>(Xah_), *xal = sym<bf>(Xal_);
    bf *xbh = sym<bf>(Xbh_), *xbl = sym<bf>(Xbl_);
    bf *yh = sym<bf>(Yh_), *yl = sym<bf>(Yl_);
    bf *fkh = sym<bf>(FKh_), *fkl = sym<bf>(FKl_);
    bf *fkth = sym<bf>(FKTh_), *fktl = sym<bf>(FKTl_);
    bf *ghh = sym<bf>(Gh_), *gll = sym<bf>(Gl_);
    bf *wah = sym<bf>(Wah_), *wal = sym<bf>(Wal_);
    bf *wbh = sym<bf>(Wbh_), *wbl = sym<bf>(Wbl_);

    // fused prep (+ y zero)
    {
        long total = (long)NN*NB + (long)NN*HIDD + (long)HIDD*HIDD + (long)HIDD*DD
                   + (long)NC*NN + (long)NC*DD + (long)NC*DD + (long)NB*NC;
        prep_all<<<(int)((total + 255) / 256), 256>>>(
            X0, W1, W2, W3, H0, F,
            x0th, x0tl, w1th, w1tl, w2th, w2tl, w3th, w3tl,
            h0h, h0l, fh, fl, fth, ftl, pyf);
    }
    init_sync<<<1, 1>>>();

    // MLP head
    tg(x0th, x0tl, w1th, w1tl, nullptr, h1h, h1l, HIDD, 1, NB, HIDD, NN, 1, b1);
    tg(h1h, h1l, w2th, w2tl, nullptr, h2h, h2l, HIDD, 1, NB, HIDD, HIDD, 1, b2);
    tg(h2h, h2l, w3th, w3tl, nullptr, vh, vl, DD, 1, NB, DD, HIDD, 2, b3, ubar);

    // b = g + X0^T H0^T
    tg(x0th, x0tl, h0h, h0l, pbf, nullptr, nullptr, NC, 1, NB, NC, NN, 3, gg);

    // K = 2I + F^T F
    tg(fth, ftl, fth, ftl, pKf, kh, kl, DD, 1, DD, DD, NC, 7);

    // Kinv: Newton-Schulz
    gershgorin_kernel<<<1, 512>>>(pKf, DD);
    init_diag_split<<<(DD*DD + 255)/256, 256>>>(pXaf, xah, xal, DD);
    {
        float *Xcf = pXaf, *Xnf = pXbf;
        bf *Xch = xah, *Xcl = xal, *Xnh = xbh, *Xnl = xbl;
        for (int t = 0; t < NEWTON_ITERS; t++) {
            tg(Xch, Xcl, kh, kl, nullptr, yh, yl, DD, 1, DD, DD, DD, 0);
            tg(yh, yl, Xch, Xcl, Xnf, Xnh, Xnl, DD, 1, DD, DD, DD, 8, Xcf);
            float* tf = Xcf; Xcf = Xnf; Xnf = tf;
            bf* t1 = Xch; Xch = Xnh; Xnh = t1;
            bf* t2 = Xcl; Xcl = Xnl; Xnl = t2;
        }
        // even iters -> Kinv in xah/xal
    }

    // precompute: FK, FKT, G, C
    tg(fh, fl, xah, xal, pFKf, fkh, fkl, DD, 1, NC, DD, DD, 0);
    transpose_split<<<(NC*DD + 255)/256, 256>>>(pFKf, fkth, fktl, NC, DD);
    tg(fkh, fkl, fh, fl, nullptr, ghh, gll, NC, 1, NC, NC, DD, 0);
    tg(vh, vl, fkh, fkl, pCf, nullptr, nullptr, NC, 1, NB, NC, DD, 6);

    // init: w0 = min(V F^T, b)
    tg(vh, vl, fh, fl, nullptr, wah, wal, NC, 1, NB, NC, DD, 4, pbf);

    // ADMM: single persistent kernel, 40 iterations, grid barrier between
    {
        dim3 grid(ADMM_GRID_X, ADMM_GRID_Y);
        admm_persist<<<grid, 256, SMEMB>>>(ghh, gll, pCf, pbf, pyf,
                                           wah, wal, wbh, wbl);
        // ADMM_ITERS even -> final w in wah/wal
    }

    // u = 2 V Kinv + w FK ; out = u^T
    tg(vh, vl, xah, xal, pUf, nullptr, nullptr, DD, 1, NB, DD, DD, 6);
    tg(wah, wal, fkth, fktl, out, nullptr, nullptr, 1, NB, NB, DD, NC, 9, pUf);
}

// round 13
// speedup vs baseline: 3.3113x; 1.1555x over previous
#include <cuda_runtime.h>
#include <cuda_bf16.h>
#include <math.h>
#include <stdint.h>

#define NB   1024
#define NN   32
#define HIDD 512
#define DD   400
#define NC   800
#define ADMM_ITERS 40
#define NEWTON_ITERS 8

typedef __nv_bfloat16 bf;

// ---------------- device scratch ----------------
__device__ float g_alpha;
__device__ unsigned g_cnt1, g_gen1, g_cnt2, g_gen2;
__device__ float dKf[DD*DD];
__device__ float dXaf[DD*DD], dXbf[DD*DD];
__device__ float dFKf[NC*DD];
__device__ float dCf_[NB*NC];
__device__ float dbf_[NB*NC];
__device__ float dyf_[NB*NC];
__device__ float dUf_[NB*DD];

__device__ bf X0Th[NB*NN], X0Tl[NB*NN];
__device__ bf W1Th[HIDD*NN], W1Tl[HIDD*NN];
__device__ bf W2Th[HIDD*HIDD], W2Tl[HIDD*HIDD];
__device__ bf W3Th[DD*HIDD], W3Tl[DD*HIDD];
__device__ bf H0h_[NC*NN], H0l_[NC*NN];
__device__ bf Fh_[NC*DD], Fl_[NC*DD];
__device__ bf FTh_[DD*NC], FTl_[DD*NC];
__device__ bf H1h_[NB*HIDD], H1l_[NB*HIDD];
__device__ bf H2h_[NB*HIDD], H2l_[NB*HIDD];
__device__ bf Vh_[NB*DD], Vl_[NB*DD];
__device__ bf Kh_[DD*DD], Kl_[DD*DD];
__device__ bf Xah_[DD*DD], Xal_[DD*DD];
__device__ bf Xbh_[DD*DD], Xbl_[DD*DD];
__device__ bf Yh_[DD*DD], Yl_[DD*DD];
__device__ bf FKh_[NC*DD], FKl_[NC*DD];
__device__ bf FKTh_[DD*NC], FKTl_[DD*NC];
__device__ bf Gh_[NC*NC], Gl_[NC*NC];
__device__ bf Wah_[NB*NC], Wal_[NB*NC];
__device__ bf Wbh_[NB*NC], Wbl_[NB*NC];

// ---------------- PTX helpers ----------------
__device__ __forceinline__ uint32_t smem_u32(const void* p) {
    uint32_t a;
    asm("{ .reg .u64 t; cvta.to.shared.u64 t, %1; cvt.u32.u64 %0, t; }" : "=r"(a) : "l"(p));
    return a;
}
__device__ __forceinline__ void cp16(uint32_t sa, const void* g, int bytes) {
    asm volatile("cp.async.cg.shared.global [%0], [%1], 16, %2;"
                 :: "r"(sa), "l"(g), "r"(bytes) : "memory");
}
#define CP_COMMIT() asm volatile("cp.async.commit_group;" ::: "memory")
#define CP_WAIT1()  asm volatile("cp.async.wait_group 1;" ::: "memory")
#define CP_WAIT0()  asm volatile("cp.async.wait_group 0;" ::: "memory")

__device__ __forceinline__ void ldsm4(uint32_t* r, uint32_t a) {
    asm volatile("ldmatrix.sync.aligned.m8n8.x4.shared.b16 {%0,%1,%2,%3}, [%4];"
                 : "=r"(r[0]), "=r"(r[1]), "=r"(r[2]), "=r"(r[3]) : "r"(a));
}
__device__ __forceinline__ void mma2(float* c, uint32_t a0, uint32_t a1, uint32_t a2,
                                     uint32_t a3, uint32_t b0, uint32_t b1) {
    asm volatile("mma.sync.aligned.m16n8k16.row.col.f32.bf16.bf16.f32 "
                 "{%0,%1,%2,%3},{%4,%5,%6,%7},{%8,%9},{%0,%1,%2,%3};"
                 : "+f"(c[0]), "+f"(c[1]), "+f"(c[2]), "+f"(c[3])
                 : "r"(a0), "r"(a1), "r"(a2), "r"(a3), "r"(b0), "r"(b1));
}
#define SWZ(x) ((x) ^ (((x) >> 3) & 0x70))

__device__ __forceinline__ void gbar(unsigned* cnt, unsigned* gen, unsigned nblk,
                                     unsigned target) {
    __threadfence();
    __syncthreads();
    if (threadIdx.x == 0) {
        unsigned t = atomicAdd(cnt, 1u);
        if (t == nblk - 1u) {
            *cnt = 0u;
            __threadfence();
            atomicAdd(gen, 1u);
        } else {
            while (atomicAdd(gen, 0u) < target) { }
        }
    }
    __syncthreads();
}

// ---------------- generic tensor GEMM (BM=BN=64, 256 thr) ----------------
#define A_HALF (64 * 128)
#define B_HALF (64 * 128)
#define STAGE (2 * A_HALF + 2 * B_HALF)
#define SMEMB (3 * STAGE)

__global__ __launch_bounds__(256, 2) void tgemm(
    const bf* __restrict__ Ah, const bf* __restrict__ Al,
    const bf* __restrict__ Bh, const bf* __restrict__ Bl,
    float* __restrict__ Cf, bf* __restrict__ Ch, bf* __restrict__ Cl,
    long Crs, long Ccs,
    int Md, int Nd, int Kd,
    int epi, const float* __restrict__ e0, const float* __restrict__ e1,
    const float* __restrict__ e2, float* __restrict__ o1)
{
    extern __shared__ char sm[];
    const uint32_t sbase = smem_u32(sm);
    const int tid = threadIdx.x;
    const int wid = tid >> 5, lane = tid & 31;
    const int wm = wid >> 2, wn = wid & 3;
    const int i0 = blockIdx.y * 64, j0 = blockIdx.x * 64;
    const int nch = (Kd + 63) >> 6;

    auto fill = [&](int c) {
        const uint32_t st = sbase + (c % 3) * STAGE;
        const int k0 = c << 6;
#pragma unroll
        for (int t = 0; t < 4; t++) {
            int idx = tid + t * 256;
            int seg = idx & 7, r = (idx >> 3) & 63;
            int mat = idx >> 9;
            int gi = i0 + r, gk = k0 + seg * 8;
            bool ok = (gi < Md) && (gk < Kd);
            const bf* src = (mat ? Al : Ah) + (long)gi * Kd + gk;
            cp16(st + mat * A_HALF + SWZ((uint32_t)(r * 128 + seg * 16)),
                 ok ? (const void*)src : (const void*)Ah, ok ? 16 : 0);
        }
#pragma unroll
        for (int t = 0; t < 4; t++) {
            int idx = tid + t * 256;
            int seg = idx & 7, r = (idx >> 3) & 63;
            int mat = idx >> 9;
            int gj = j0 + r, gk = k0 + seg * 8;
            bool ok = (gj < Nd) && (gk < Kd);
            const bf* src = (mat ? Bl : Bh) + (long)gj * Kd + gk;
            cp16(st + 2 * A_HALF + mat * B_HALF + SWZ((uint32_t)(r * 128 + seg * 16)),
                 ok ? (const void*)src : (const void*)Bh, ok ? 16 : 0);
        }
    };

    float acc[2][2][4];
#pragma unroll
    for (int a = 0; a < 2; a++)
#pragma unroll
        for (int b = 0; b < 2; b++)
#pragma unroll
            for (int r = 0; r < 4; r++) acc[a][b][r] = 0.f;

    const uint32_t arow = (uint32_t)((wm * 32 + (lane & 15)) * 128 + (lane >> 4) * 16);
    const uint32_t brow = (uint32_t)((wn * 16 + (lane & 15)) * 128 + (lane >> 4) * 16);

    fill(0); CP_COMMIT();
    if (nch > 1) fill(1);
    CP_COMMIT();

    for (int c = 0; c < nch; c++) {
        CP_WAIT1();
        __syncthreads();
        if (c + 2 < nch) fill(c + 2);
        CP_COMMIT();

        const uint32_t st = sbase + (c % 3) * STAGE;
#pragma unroll
        for (int ks = 0; ks < 4; ks++) {
            uint32_t bh_[4], bl_[4], ah_[2][4], al_[2][4];
            ldsm4(bh_, st + 2 * A_HALF + SWZ(brow + ks * 32));
            ldsm4(bl_, st + 2 * A_HALF + B_HALF + SWZ(brow + ks * 32));
#pragma unroll
            for (int mt = 0; mt < 2; mt++) {
                ldsm4(ah_[mt], st + SWZ(arow + mt * 2048 + ks * 32));
                ldsm4(al_[mt], st + A_HALF + SWZ(arow + mt * 2048 + ks * 32));
            }
#pragma unroll
            for (int mt = 0; mt < 2; mt++) {
                mma2(acc[mt][0], ah_[mt][0], ah_[mt][1], ah_[mt][2], ah_[mt][3], bh_[0], bh_[2]);
                mma2(acc[mt][1], ah_[mt][0], ah_[mt][1], ah_[mt][2], ah_[mt][3], bh_[1], bh_[3]);
            }
#pragma unroll
            for (int mt = 0; mt < 2; mt++) {
                mma2(acc[mt][0], ah_[mt][0], ah_[mt][1], ah_[mt][2], ah_[mt][3], bl_[0], bl_[2]);
                mma2(acc[mt][1], ah_[mt][0], ah_[mt][1], ah_[mt][2], ah_[mt][3], bl_[1], bl_[3]);
            }
#pragma unroll
            for (int mt = 0; mt < 2; mt++) {
                mma2(acc[mt][0], al_[mt][0], al_[mt][1], al_[mt][2], al_[mt][3], bh_[0], bh_[2]);
                mma2(acc[mt][1], al_[mt][0], al_[mt][1], al_[mt][2], al_[mt][3], bh_[1], bh_[3]);
            }
        }
    }

    const int rbase = i0 + wm * 32 + (lane >> 2);
    const int cb = j0 + wn * 16 + (lane & 3) * 2;
#pragma unroll
    for (int mt = 0; mt < 2; mt++) {
#pragma unroll
        for (int nt = 0; nt < 2; nt++) {
#pragma unroll
            for (int rr = 0; rr < 2; rr++) {
#pragma unroll
                for (int cc = 0; cc < 2; cc++) {
                    int i = rbase + mt * 16 + rr * 8;
                    int j = cb + nt * 8 + cc;
                    if (i >= Md || j >= Nd) continue;
                    float v = acc[mt][nt][rr * 2 + cc];
                    long rm = (long)i * Nd + j;
                    float out;
                    switch (epi) {
                        default:
                        case 0: out = v; break;
                        case 1: out = fmaxf(v + e0[j], 0.f); break;
                        case 2: out = tanhf(v + e0[j]) * e1[j & 7]; break;
                        case 3: out = v + e0[j]; break;
                        case 4: out = fminf(v, e0[rm]); break;
                        case 6: out = 2.f * v; break;
                        case 7: out = (i == j) ? v + 2.f : v; break;
                        case 9: out = v + e0[rm]; break;
                    }
                    if (Cf) Cf[(long)i * Crs + (long)j * Ccs] = out;
                    if (Ch) {
                        bf h16 = __float2bfloat16(out);
                        Ch[rm] = h16;
                        Cl[rm] = __float2bfloat16(out - __bfloat162float(h16));
                    }
                }
            }
        }
    }
    CP_WAIT0();
}

// ---------------- persistent ADMM: BM=64, BN=32, 128 thr, 296 CTAs ----------------
#define AD_TN 25
#define AD_TILES 400
#define AD_BLK 296
#define AD_AH (64 * 128)
#define AD_BH (32 * 128)
#define AD_STG (2 * AD_AH + 2 * AD_BH)
#define AD_SMEM (3 * AD_STG)
#define NCH_ADMM 13

__global__ __launch_bounds__(128, 3) void admm_persist(
    const bf* __restrict__ Gh, const bf* __restrict__ Gl,
    const float* __restrict__ Cf, const float* __restrict__ bfv,
    float* __restrict__ yf,
    bf* __restrict__ wah, bf* __restrict__ wal,
    bf* __restrict__ wbh, bf* __restrict__ wbl)
{
    extern __shared__ char sm[];
    const uint32_t sbase = smem_u32(sm);
    const int tid = threadIdx.x;
    const int wid = tid >> 5, lane = tid & 31;
    const int wm = wid >> 1, wn = wid & 1;

    const uint32_t arow = (uint32_t)((wm * 32 + (lane & 15)) * 128 + (lane >> 4) * 16);
    const uint32_t brow = (uint32_t)((wn * 16 + (lane & 15)) * 128 + (lane >> 4) * 16);

    for (int t = 0; t < ADMM_ITERS; t++) {
        const bf* Ah = (t & 1) ? wbh : wah;
        const bf* Al = (t & 1) ? wbl : wal;
        bf* Oh = (t & 1) ? wah : wbh;
        bf* Ol = (t & 1) ? wal : wbl;

        for (int tile = blockIdx.x; tile < AD_TILES; tile += AD_BLK) {
            const int i0 = (tile / AD_TN) * 64;
            const int j0 = (tile % AD_TN) * 32;

            auto fill = [&](int c) {
                const uint32_t st = sbase + (c % 3) * AD_STG;
                const int k0 = c << 6;
#pragma unroll
                for (int it = 0; it < 8; it++) {
                    int idx = tid + it * 128;
                    int seg = idx & 7, r = (idx >> 3) & 63;
                    int mat = idx >> 9;
                    int gi = i0 + r, gk = k0 + seg * 8;
                    bool ok = gk < NC;
                    const bf* src = (mat ? Al : Ah) + (long)gi * NC + gk;
                    cp16(st + mat * AD_AH + SWZ((uint32_t)(r * 128 + seg * 16)),
                         ok ? (const void*)src : (const void*)Ah, ok ? 16 : 0);
                }
#pragma unroll
                for (int it = 0; it < 4; it++) {
                    int idx = tid + it * 128;
                    int seg = idx & 7, r = (idx >> 3) & 31;
                    int mat = idx >> 8;
                    int gj = j0 + r, gk = k0 + seg * 8;
                    bool ok = gk < NC;
                    const bf* src = (mat ? Gl : Gh) + (long)gj * NC + gk;
                    cp16(st + 2 * AD_AH + mat * AD_BH + SWZ((uint32_t)(r * 128 + seg * 16)),
                         ok ? (const void*)src : (const void*)Gh, ok ? 16 : 0);
                }
            };

            float acc[2][2][4];
#pragma unroll
            for (int a = 0; a < 2; a++)
#pragma unroll
                for (int b = 0; b < 2; b++)
#pragma unroll
                    for (int r = 0; r < 4; r++) acc[a][b][r] = 0.f;

            fill(0); CP_COMMIT();
            fill(1); CP_COMMIT();

            uint32_t ah_[2][2][4], al_[2][2][4], bh_[2][4], bl_[2][4];

            for (int c = 0; c < NCH_ADMM; c++) {
                CP_WAIT1();
                __syncthreads();
                if (c + 2 < NCH_ADMM) fill(c + 2);
                CP_COMMIT();

                const uint32_t st = sbase + (c % 3) * AD_STG;
                ldsm4(bh_[0], st + 2 * AD_AH + SWZ(brow));
                ldsm4(bl_[0], st + 2 * AD_AH + AD_BH + SWZ(brow));
#pragma unroll
                for (int mt = 0; mt < 2; mt++) {
                    ldsm4(ah_[0][mt], st + SWZ(arow + mt * 2048));
                    ldsm4(al_[0][mt], st + AD_AH + SWZ(arow + mt * 2048));
                }
#pragma unroll
                for (int ks = 0; ks < 4; ks++) {
                    const int cur = ks & 1, nxt = cur ^ 1;
                    if (ks < 3) {
                        ldsm4(bh_[nxt], st + 2 * AD_AH + SWZ(brow + (ks + 1) * 32));
                        ldsm4(bl_[nxt], st + 2 * AD_AH + AD_BH + SWZ(brow + (ks + 1) * 32));
#pragma unroll
                        for (int mt = 0; mt < 2; mt++) {
                            ldsm4(ah_[nxt][mt], st + SWZ(arow + mt * 2048 + (ks + 1) * 32));
                            ldsm4(al_[nxt][mt], st + AD_AH + SWZ(arow + mt * 2048 + (ks + 1) * 32));
                        }
                    }
#pragma unroll
                    for (int mt = 0; mt < 2; mt++) {
                        mma2(acc[mt][0], ah_[cur][mt][0], ah_[cur][mt][1], ah_[cur][mt][2],
                             ah_[cur][mt][3], bh_[cur][0], bh_[cur][2]);
                        mma2(acc[mt][1], ah_[cur][mt][0], ah_[cur][mt][1], ah_[cur][mt][2],
                             ah_[cur][mt][3], bh_[cur][1], bh_[cur][3]);
                    }
#pragma unroll
                    for (int mt = 0; mt < 2; mt++) {
                        mma2(acc[mt][0], ah_[cur][mt][0], ah_[cur][mt][1], ah_[cur][mt][2],
                             ah_[cur][mt][3], bl_[cur][0], bl_[cur][2]);
                        mma2(acc[mt][1], ah_[cur][mt][0], ah_[cur][mt][1], ah_[cur][mt][2],
                             ah_[cur][mt][3], bl_[cur][1], bl_[cur][3]);
                    }
#pragma unroll
                    for (int mt = 0; mt < 2; mt++) {
                        mma2(acc[mt][0], al_[cur][mt][0], al_[cur][mt][1], al_[cur][mt][2],
                             al_[cur][mt][3], bh_[cur][0], bh_[cur][2]);
                        mma2(acc[mt][1], al_[cur][mt][0], al_[cur][mt][1], al_[cur][mt][2],
                             al_[cur][mt][3], bh_[cur][1], bh_[cur][3]);
                    }
                }
            }
            CP_WAIT0();

            const int rbase = i0 + wm * 32 + (lane >> 2);
            const int cb = j0 + wn * 16 + (lane & 3) * 2;
#pragma unroll
            for (int mt = 0; mt < 2; mt++) {
#pragma unroll
                for (int nt = 0; nt < 2; nt++) {
#pragma unroll
                    for (int rr = 0; rr < 2; rr++) {
                        int i = rbase + mt * 16 + rr * 8;
                        int j = cb + nt * 8;
                        long rm = (long)i * NC + j;
                        float2 cf = *(const float2*)&Cf[rm];
                        float2 yv = *(const float2*)&yf[rm];
                        float2 bv = *(const float2*)&bfv[rm];
                        float s0 = acc[mt][nt][rr * 2 + 0] + cf.x + yv.x;
                        float s1 = acc[mt][nt][rr * 2 + 1] + cf.y + yv.y;
                        float yn0 = fmaxf(s0 - bv.x, 0.f);
                        float yn1 = fmaxf(s1 - bv.y, 0.f);
                        float o0 = s0 - 2.f * yn0;
                        float o1v = s1 - 2.f * yn1;
                        *(float2*)&yf[rm] = make_float2(yn0, yn1);
                        bf h0 = __float2bfloat16(o0);
                        bf h1 = __float2bfloat16(o1v);
                        bf l0 = __float2bfloat16(o0 - __bfloat162float(h0));
                        bf l1 = __float2bfloat16(o1v - __bfloat162float(h1));
                        uint32_t ph = ((uint32_t)*(uint16_t*)&h1 << 16) | *(uint16_t*)&h0;
                        uint32_t pl = ((uint32_t)*(uint16_t*)&l1 << 16) | *(uint16_t*)&l0;
                        *(uint32_t*)&Oh[rm] = ph;
                        *(uint32_t*)&Ol[rm] = pl;
                    }
                }
            }
        }
        if (t + 1 < ADMM_ITERS) gbar(&g_cnt1, &g_gen1, AD_BLK, (unsigned)(t + 1));
    }
}

// ---------------- persistent Newton-Schulz: 32x32 tiles, 169 CTAs ----------------
#define NW_BLK 169
#define NW_AH (32 * 128)
#define NW_STG (4 * NW_AH)    // Ah, Al, Bh, Bl
#define NW_SMEM (3 * NW_STG)

__global__ __launch_bounds__(128, 4) void newton_persist(
    const bf* __restrict__ Kh, const bf* __restrict__ Kl,
    float* __restrict__ Xaf, float* __restrict__ Xbf,
    bf* __restrict__ Xah, bf* __restrict__ Xal,
    bf* __restrict__ Xbh, bf* __restrict__ Xbl,
    bf* __restrict__ Yh, bf* __restrict__ Yl)
{
    extern __shared__ char sm[];
    const uint32_t sbase = smem_u32(sm);
    const int tid = threadIdx.x;
    const int wid = tid >> 5, lane = tid & 31;
    const int wm = wid >> 1, wn = wid & 1;
    const int i0 = (blockIdx.x / 13) * 32;
    const int j0 = (blockIdx.x % 13) * 32;

    const uint32_t arow = (uint32_t)((wm * 16 + (lane & 15)) * 128 + (lane >> 4) * 16);
    const uint32_t brow = (uint32_t)((wn * 16 + (lane & 15)) * 128 + (lane >> 4) * 16);
    const int rb0 = i0 + wm * 16 + (lane >> 2);
    const int cb0 = j0 + wn * 16 + (lane & 3) * 2;

    unsigned bt = 0;

    auto run_gemm = [&](const bf* Ah, const bf* Al, const bf* Bh, const bf* Bl,
                        int mode, const float* Xcf, float* Xnf, bf* Oh, bf* Ol) {
        auto fill = [&](int c) {
            const uint32_t st = sbase + (c % 3) * NW_STG;
            const int k0 = c << 6;
#pragma unroll
            for (int it = 0; it < 4; it++) {
                int idx = tid + it * 128;
                int seg = idx & 7, r = (idx >> 3) & 31;
                int mat = idx >> 8;
                int gi = i0 + r, gk = k0 + seg * 8;
                bool ok = (gi < DD) && (gk < DD);
                const bf* src = (mat ? Al : Ah) + (long)gi * DD + gk;
                cp16(st + mat * NW_AH + SWZ((uint32_t)(r * 128 + seg * 16)),
                     ok ? (const void*)src : (const void*)Ah, ok ? 16 : 0);
            }
#pragma unroll
            for (int it = 0; it < 4; it++) {
                int idx = tid + it * 128;
                int seg = idx & 7, r = (idx >> 3) & 31;
                int mat = idx >> 8;
                int gj = j0 + r, gk = k0 + seg * 8;
                bool ok = (gj < DD) && (gk < DD);
                const bf* src = (mat ? Bl : Bh) + (long)gj * DD + gk;
                cp16(st + 2 * NW_AH + mat * NW_AH + SWZ((uint32_t)(r * 128 + seg * 16)),
                     ok ? (const void*)src : (const void*)Bh, ok ? 16 : 0);
            }
        };

        float acc[2][4];
#pragma unroll
        for (int b = 0; b < 2; b++)
#pragma unroll
            for (int r = 0; r < 4; r++) acc[b][r] = 0.f;

        const int nch = 7;   // ceil(400/64)
        fill(0); CP_COMMIT();
        fill(1); CP_COMMIT();

        for (int c = 0; c < nch; c++) {
            CP_WAIT1();
            __syncthreads();
            if (c + 2 < nch) fill(c + 2);
            CP_COMMIT();

            const uint32_t st = sbase + (c % 3) * NW_STG;
#pragma unroll
            for (int ks = 0; ks < 4; ks++) {
                uint32_t ah_[4], al_[4], bh_[4], bl_[4];
                ldsm4(bh_, st + 2 * NW_AH + SWZ(brow + ks * 32));
                ldsm4(bl_, st + 3 * NW_AH + SWZ(brow + ks * 32));
                ldsm4(ah_, st + SWZ(arow + ks * 32));
                ldsm4(al_, st + NW_AH + SWZ(arow + ks * 32));
                mma2(acc[0], ah_[0], ah_[1], ah_[2], ah_[3], bh_[0], bh_[2]);
                mma2(acc[1], ah_[0], ah_[1], ah_[2], ah_[3], bh_[1], bh_[3]);
                mma2(acc[0], ah_[0], ah_[1], ah_[2], ah_[3], bl_[0], bl_[2]);
                mma2(acc[1], ah_[0], ah_[1], ah_[2], ah_[3], bl_[1], bl_[3]);
                mma2(acc[0], al_[0], al_[1], al_[2], al_[3], bh_[0], bh_[2]);
                mma2(acc[1], al_[0], al_[1], al_[2], al_[3], bh_[1], bh_[3]);
            }
        }
        CP_WAIT0();

#pragma unroll
        for (int nt = 0; nt < 2; nt++) {
#pragma unroll
            for (int rr = 0; rr < 2; rr++) {
                int i = rb0 + rr * 8;
                int j = cb0 + nt * 8;
                if (i >= DD || j >= DD) continue;
                long rm = (long)i * DD + j;
                float v0 = acc[nt][rr * 2 + 0];
                float v1 = acc[nt][rr * 2 + 1];
                float o0, o1v;
                if (mode == 0) { o0 = v0; o1v = v1; }
                else {
                    float2 xc = *(const float2*)&Xcf[rm];
                    o0 = 2.f * xc.x - v0;
                    o1v = 2.f * xc.y - v1;
                    *(float2*)&Xnf[rm] = make_float2(o0, o1v);
                }
                bf h0 = __float2bfloat16(o0);
                bf h1 = __float2bfloat16(o1v);
                bf l0 = __float2bfloat16(o0 - __bfloat162float(h0));
                bf l1 = __float2bfloat16(o1v - __bfloat162float(h1));
                uint32_t ph = ((uint32_t)*(uint16_t*)&h1 << 16) | *(uint16_t*)&h0;
                uint32_t pl = ((uint32_t)*(uint16_t*)&l1 << 16) | *(uint16_t*)&l0;
                *(uint32_t*)&Oh[rm] = ph;
                *(uint32_t*)&Ol[rm] = pl;
            }
        }
    };

    for (int it = 0; it < NEWTON_ITERS; it++) {
        const bf* Ach = (it & 1) ? Xbh : Xah;
        const bf* Acl = (it & 1) ? Xbl : Xal;
        const float* Xcf = (it & 1) ? Xbf : Xaf;
        float* Xnf = (it & 1) ? Xaf : Xbf;
        bf* Xnh = (it & 1) ? Xah : Xbh;
        bf* Xnl = (it & 1) ? Xal : Xbl;

        run_gemm(Ach, Acl, Kh, Kl, 0, nullptr, nullptr, Yh, Yl);
        gbar(&g_cnt2, &g_gen2, NW_BLK, ++bt);
        run_gemm(Yh, Yl, Ach, Acl, 1, Xcf, Xnf, Xnh, Xnl);
        if (it + 1 < NEWTON_ITERS) gbar(&g_cnt2, &g_gen2, NW_BLK, ++bt);
    }
    // NEWTON_ITERS even -> final inverse in Xa (f/h/l)
}

// ---------------- prep / small kernels ----------------
__device__ __forceinline__ void split_one(float x, bf* h, bf* l, long o) {
    bf b = __float2bfloat16(x);
    h[o] = b;
    l[o] = __float2bfloat16(x - __bfloat162float(b));
}
__global__ void prep_all(const float* __restrict__ X0, const float* __restrict__ W1,
                         const float* __restrict__ W2, const float* __restrict__ W3,
                         const float* __restrict__ H0, const float* __restrict__ F,
                         bf* x0th, bf* x0tl, bf* w1th, bf* w1tl, bf* w2th, bf* w2tl,
                         bf* w3th, bf* w3tl, bf* h0h, bf* h0l, bf* fh, bf* fl,
                         bf* fth, bf* ftl, float* yzero)
{
    long idx = (long)blockIdx.x * blockDim.x + threadIdx.x;
    const long n0 = NN * NB, n1 = NN * HIDD, n2 = HIDD * HIDD, n3 = HIDD * DD;
    const long n4 = NC * NN, n5 = (long)NC * DD, n6 = (long)NC * DD;
    const long n7 = (long)NB * NC;
    if (idx < n0) {
        int r = idx / NB, c = idx - (long)r * NB;
        split_one(X0[idx], x0th, x0tl, (long)c * NN + r);
        return;
    }
    idx -= n0;
    if (idx < n1) {
        int r = idx / HIDD, c = idx - (long)r * HIDD;
        split_one(W1[idx], w1th, w1tl, (long)c * NN + r);
        return;
    }
    idx -= n1;
    if (idx < n2) {
        int r = idx / HIDD, c = idx - (long)r * HIDD;
        split_one(W2[idx], w2th, w2tl, (long)c * HIDD + r);
        return;
    }
    idx -= n2;
    if (idx < n3) {
        int r = idx / DD, c = idx - (long)r * DD;
        split_one(W3[idx], w3th, w3tl, (long)c * HIDD + r);
        return;
    }
    idx -= n3;
    if (idx < n4) { split_one(H0[idx], h0h, h0l, idx); return; }
    idx -= n4;
    if (idx < n5) { split_one(F[idx], fh, fl, idx); return; }
    idx -= n5;
    if (idx < n6) {
        int r = idx / DD, c = idx - (long)r * DD;
        split_one(F[idx], fth, ftl, (long)c * NC + r);
        return;
    }
    idx -= n6;
    if (idx < n7) { yzero[idx] = 0.f; return; }
}
__global__ void init_sync() { g_cnt1 = 0u; g_gen1 = 0u; g_cnt2 = 0u; g_gen2 = 0u; }
__global__ void transpose_split(const float* __restrict__ s, bf* __restrict__ h,
                                bf* __restrict__ l, int R, int C) {
    long i = (long)blockIdx.x * blockDim.x + threadIdx.x;
    if (i < (long)R * C) {
        int r = i / C, c = i - (long)r * C;
        split_one(s[i], h, l, (long)c * R + r);
    }
}
__global__ void gershgorin_kernel(const float* __restrict__ K, int n) {
    __shared__ float red[512];
    float mx = 0.f;
    for (int i = threadIdx.x; i < n; i += blockDim.x) {
        float sum = 0.f;
        for (int j = 0; j < n; j++) sum += fabsf(K[i * n + j]);
        mx = fmaxf(mx, sum);
    }
    red[threadIdx.x] = mx;
    __syncthreads();
    for (int s = 256; s > 0; s >>= 1) {
        if (threadIdx.x < s) red[threadIdx.x] = fmaxf(red[threadIdx.x], red[threadIdx.x + s]);
        __syncthreads();
    }
    if (threadIdx.x == 0) g_alpha = 2.f / (2.f + red[0]);
}
__global__ void init_diag_split(float* __restrict__ Xf, bf* __restrict__ Xh,
                                bf* __restrict__ Xl, int n) {
    int idx = blockIdx.x * blockDim.x + threadIdx.x;
    if (idx < n * n) {
        int i = idx / n, j = idx - i * n;
        float v = (i == j) ? g_alpha : 0.f;
        Xf[idx] = v;
        bf b = __float2bfloat16(v);
        Xh[idx] = b;
        Xl[idx] = __float2bfloat16(v - __bfloat162float(b));
    }
}

// ---------------- host ----------------
static inline void tg(const bf* Ah, const bf* Al, const bf* Bh, const bf* Bl,
                      float* Cf, bf* Ch, bf* Cl, long Crs, long Ccs,
                      int M, int N, int K, int epi,
                      const float* e0 = nullptr, const float* e1 = nullptr,
                      const float* e2 = nullptr, float* o1 = nullptr)
{
    dim3 grid((N + 63) / 64, (M + 63) / 64);
    tgemm<<<grid, 256, SMEMB>>>(Ah, Al, Bh, Bl, Cf, Ch, Cl, Crs, Ccs,
                                M, N, K, epi, e0, e1, e2, o1);
}

template <typename T> static inline T* sym(const void* s) {
    void* p = nullptr;
    cudaGetSymbolAddress(&p, s);
    return (T*)p;
}

extern "C" void kernel_launch(void* const* d_in, const int* in_sizes, int n_in,
                              void* d_out, int out_size)
{
    const float* X0   = (const float*)d_in[0];
    const float* W1   = (const float*)d_in[1];
    const float* b1   = (const float*)d_in[2];
    const float* W2   = (const float*)d_in[3];
    const float* b2   = (const float*)d_in[4];
    const float* W3   = (const float*)d_in[5];
    const float* b3   = (const float*)d_in[6];
    const float* ubar = (const float*)d_in[7];
    const float* F    = (const float*)d_in[8];
    const float* gg   = (const float*)d_in[9];
    const float* H0   = (const float*)d_in[10];
    float* out = (float*)d_out;

    cudaFuncSetAttribute(tgemm, cudaFuncAttributeMaxDynamicSharedMemorySize, SMEMB);
    cudaFuncSetAttribute(admm_persist, cudaFuncAttributeMaxDynamicSharedMemorySize, AD_SMEM);
    cudaFuncSetAttribute(newton_persist, cudaFuncAttributeMaxDynamicSharedMemorySize, NW_SMEM);

    float *pKf = sym<float>(dKf), *pXaf = sym<float>(dXaf), *pXbf = sym<float>(dXbf);
    float *pFKf = sym<float>(dFKf), *pCf = sym<float>(dCf_), *pbf = sym<float>(dbf_);
    float *pyf = sym<float>(dyf_), *pUf = sym<float>(dUf_);

    bf *x0th = sym<bf>(X0Th), *x0tl = sym<bf>(X0Tl);
    bf *w1th = sym<bf>(W1Th), *w1tl = sym<bf>(W1Tl);
    bf *w2th = sym<bf>(W2Th), *w2tl = sym<bf>(W2Tl);
    bf *w3th = sym<bf>(W3Th), *w3tl = sym<bf>(W3Tl);
    bf *h0h = sym<bf>(H0h_), *h0l = sym<bf>(H0l_);
    bf *fh = sym<bf>(Fh_), *fl = sym<bf>(Fl_);
    bf *fth = sym<bf>(FTh_), *ftl = sym<bf>(FTl_);
    bf *h1h = sym<bf>(H1h_), *h1l = sym<bf>(H1l_);
    bf *h2h = sym<bf>(H2h_), *h2l = sym<bf>(H2l_);
    bf *vh = sym<bf>(Vh_), *vl = sym<bf>(Vl_);
    bf *kh = sym<bf>(Kh_), *kl = sym<bf>(Kl_);
    bf *xah = sym<bf>(Xah_), *xal = sym<bf>(Xal_);
    bf *xbh = sym<bf>(Xbh_), *xbl = sym<bf>(Xbl_);
    bf *yh = sym<bf>(Yh_), *yl = sym<bf>(Yl_);
    bf *fkh = sym<bf>(FKh_), *fkl = sym<bf>(FKl_);
    bf *fkth = sym<bf>(FKTh_), *fktl = sym<bf>(FKTl_);
    bf *ghh = sym<bf>(Gh_), *gll = sym<bf>(Gl_);
    bf *wah = sym<bf>(Wah_), *wal = sym<bf>(Wal_);
    bf *wbh = sym<bf>(Wbh_), *wbl = sym<bf>(Wbl_);

    // fused prep (+ y zero) + sync counters
    {
        long total = (long)NN*NB + (long)NN*HIDD + (long)HIDD*HIDD + (long)HIDD*DD
                   + (long)NC*NN + (long)NC*DD + (long)NC*DD + (long)NB*NC;
        prep_all<<<(int)((total + 255) / 256), 256>>>(
            X0, W1, W2, W3, H0, F,
            x0th, x0tl, w1th, w1tl, w2th, w2tl, w3th, w3tl,
            h0h, h0l, fh, fl, fth, ftl, pyf);
    }
    init_sync<<<1, 1>>>();

    // MLP head
    tg(x0th, x0tl, w1th, w1tl, nullptr, h1h, h1l, HIDD, 1, NB, HIDD, NN, 1, b1);
    tg(h1h, h1l, w2th, w2tl, nullptr, h2h, h2l, HIDD, 1, NB, HIDD, HIDD, 1, b2);
    tg(h2h, h2l, w3th, w3tl, nullptr, vh, vl, DD, 1, NB, DD, HIDD, 2, b3, ubar);

    // b = g + X0^T H0^T
    tg(x0th, x0tl, h0h, h0l, pbf, nullptr, nullptr, NC, 1, NB, NC, NN, 3, gg);

    // K = 2I + F^T F
    tg(fth, ftl, fth, ftl, pKf, kh, kl, DD, 1, DD, DD, NC, 7);

    // Kinv: persistent Newton-Schulz (8 iters -> result in xa)
    gershgorin_kernel<<<1, 512>>>(pKf, DD);
    init_diag_split<<<(DD*DD + 255)/256, 256>>>(pXaf, xah, xal, DD);
    newton_persist<<<NW_BLK, 128, NW_SMEM>>>(kh, kl, pXaf, pXbf,
                                             xah, xal, xbh, xbl, yh, yl);

    // precompute: FK, FKT, G, C
    tg(fh, fl, xah, xal, pFKf, fkh, fkl, DD, 1, NC, DD, DD, 0);
    transpose_split<<<(NC*DD + 255)/256, 256>>>(pFKf, fkth, fktl, NC, DD);
    tg(fkh, fkl, fh, fl, nullptr, ghh, gll, NC, 1, NC, NC, DD, 0);
    tg(vh, vl, fkh, fkl, pCf, nullptr, nullptr, NC, 1, NB, NC, DD, 6);

    // init: w0 = min(V F^T, b)
    tg(vh, vl, fh, fl, nullptr, wah, wal, NC, 1, NB, NC, DD, 4, pbf);

    // ADMM: persistent, 40 iters, balanced 64x32 tiles
    admm_persist<<<AD_BLK, 128, AD_SMEM>>>(ghh, gll, pCf, pbf, pyf,
                                           wah, wal, wbh, wbl);
    // even iters -> final w in wah/wal

    // u = 2 V Kinv + w FK ; out = u^T
    tg(vh, vl, xah, xal, pUf, nullptr, nullptr, DD, 1, NB, DD, DD, 6);
    tg(wah, wal, fkth, fktl, out, nullptr, nullptr, 1, NB, NB, DD, NC, 9, pUf);
}

// round 14
// speedup vs baseline: 3.4574x; 1.0441x over previous
#include <cuda_runtime.h>
#include <cuda_bf16.h>
#include <math.h>
#include <stdint.h>

#define NB   1024
#define NN   32
#define HIDD 512
#define DD   400
#define NC   800
#define ADMM_ITERS 40
#define NEWTON_ITERS 8

typedef __nv_bfloat16 bf;

// ---------------- device scratch ----------------
__device__ float g_alpha;
__device__ unsigned g_cnt1, g_gen1, g_cnt2, g_gen2;
__device__ float dKf[DD*DD];
__device__ float dXaf[DD*DD], dXbf[DD*DD];
__device__ float dFKf[NC*DD];
__device__ float dCf_[NB*NC];
__device__ float dbf_[NB*NC];
__device__ float dyf_[NB*NC];
__device__ float dUf_[NB*DD];

__device__ bf X0Th[NB*NN], X0Tl[NB*NN];
__device__ bf W1Th[HIDD*NN], W1Tl[HIDD*NN];
__device__ bf W2Th[HIDD*HIDD], W2Tl[HIDD*HIDD];
__device__ bf W3Th[DD*HIDD], W3Tl[DD*HIDD];
__device__ bf H0h_[NC*NN], H0l_[NC*NN];
__device__ bf Fh_[NC*DD], Fl_[NC*DD];
__device__ bf FTh_[DD*NC], FTl_[DD*NC];
__device__ bf H1h_[NB*HIDD], H1l_[NB*HIDD];
__device__ bf H2h_[NB*HIDD], H2l_[NB*HIDD];
__device__ bf Vh_[NB*DD], Vl_[NB*DD];
__device__ bf Kh_[DD*DD], Kl_[DD*DD];
__device__ bf Xah_[DD*DD], Xal_[DD*DD];
__device__ bf Xbh_[DD*DD], Xbl_[DD*DD];
__device__ bf Yh_[DD*DD], Yl_[DD*DD];
__device__ bf FKh_[NC*DD], FKl_[NC*DD];
__device__ bf FKTh_[DD*NC], FKTl_[DD*NC];
__device__ bf Gh_[NC*NC], Gl_[NC*NC];
__device__ bf Wah_[NB*NC], Wal_[NB*NC];
__device__ bf Wbh_[NB*NC], Wbl_[NB*NC];

// ---------------- PTX helpers ----------------
__device__ __forceinline__ uint32_t smem_u32(const void* p) {
    uint32_t a;
    asm("{ .reg .u64 t; cvta.to.shared.u64 t, %1; cvt.u32.u64 %0, t; }" : "=r"(a) : "l"(p));
    return a;
}
__device__ __forceinline__ void cp16(uint32_t sa, const void* g, int bytes) {
    asm volatile("cp.async.cg.shared.global [%0], [%1], 16, %2;"
                 :: "r"(sa), "l"(g), "r"(bytes) : "memory");
}
#define CP_COMMIT() asm volatile("cp.async.commit_group;" ::: "memory")
#define CP_WAIT1()  asm volatile("cp.async.wait_group 1;" ::: "memory")
#define CP_WAIT0()  asm volatile("cp.async.wait_group 0;" ::: "memory")

__device__ __forceinline__ void ldsm4(uint32_t* r, uint32_t a) {
    asm volatile("ldmatrix.sync.aligned.m8n8.x4.shared.b16 {%0,%1,%2,%3}, [%4];"
                 : "=r"(r[0]), "=r"(r[1]), "=r"(r[2]), "=r"(r[3]) : "r"(a));
}
__device__ __forceinline__ void mma2(float* c, uint32_t a0, uint32_t a1, uint32_t a2,
                                     uint32_t a3, uint32_t b0, uint32_t b1) {
    asm volatile("mma.sync.aligned.m16n8k16.row.col.f32.bf16.bf16.f32 "
                 "{%0,%1,%2,%3},{%4,%5,%6,%7},{%8,%9},{%0,%1,%2,%3};"
                 : "+f"(c[0]), "+f"(c[1]), "+f"(c[2]), "+f"(c[3])
                 : "r"(a0), "r"(a1), "r"(a2), "r"(a3), "r"(b0), "r"(b1));
}
#define SWZ(x) ((x) ^ (((x) >> 3) & 0x70))

__device__ __forceinline__ void gbar(unsigned* cnt, unsigned* gen, unsigned nblk,
                                     unsigned target) {
    __threadfence();
    __syncthreads();
    if (threadIdx.x == 0) {
        unsigned t = atomicAdd(cnt, 1u);
        if (t == nblk - 1u) {
            *cnt = 0u;
            __threadfence();
            atomicAdd(gen, 1u);
        } else {
            while (atomicAdd(gen, 0u) < target) { }
        }
    }
    __syncthreads();
}

// ---------------- generic tensor GEMM (BM=BN=64, 256 thr) ----------------
#define A_HALF (64 * 128)
#define B_HALF (64 * 128)
#define STAGE (2 * A_HALF + 2 * B_HALF)
#define SMEMB (3 * STAGE)

__global__ __launch_bounds__(256, 2) void tgemm(
    const bf* __restrict__ Ah, const bf* __restrict__ Al,
    const bf* __restrict__ Bh, const bf* __restrict__ Bl,
    float* __restrict__ Cf, bf* __restrict__ Ch, bf* __restrict__ Cl,
    long Crs, long Ccs,
    int Md, int Nd, int Kd,
    int epi, const float* __restrict__ e0, const float* __restrict__ e1,
    const float* __restrict__ e2, float* __restrict__ o1)
{
    extern __shared__ char sm[];
    const uint32_t sbase = smem_u32(sm);
    const int tid = threadIdx.x;
    const int wid = tid >> 5, lane = tid & 31;
    const int wm = wid >> 2, wn = wid & 3;
    const int i0 = blockIdx.y * 64, j0 = blockIdx.x * 64;
    const int nch = (Kd + 63) >> 6;

    auto fill = [&](int c) {
        const uint32_t st = sbase + (c % 3) * STAGE;
        const int k0 = c << 6;
#pragma unroll
        for (int t = 0; t < 4; t++) {
            int idx = tid + t * 256;
            int seg = idx & 7, r = (idx >> 3) & 63;
            int mat = idx >> 9;
            int gi = i0 + r, gk = k0 + seg * 8;
            bool ok = (gi < Md) && (gk < Kd);
            const bf* src = (mat ? Al : Ah) + (long)gi * Kd + gk;
            cp16(st + mat * A_HALF + SWZ((uint32_t)(r * 128 + seg * 16)),
                 ok ? (const void*)src : (const void*)Ah, ok ? 16 : 0);
        }
#pragma unroll
        for (int t = 0; t < 4; t++) {
            int idx = tid + t * 256;
            int seg = idx & 7, r = (idx >> 3) & 63;
            int mat = idx >> 9;
            int gj = j0 + r, gk = k0 + seg * 8;
            bool ok = (gj < Nd) && (gk < Kd);
            const bf* src = (mat ? Bl : Bh) + (long)gj * Kd + gk;
            cp16(st + 2 * A_HALF + mat * B_HALF + SWZ((uint32_t)(r * 128 + seg * 16)),
                 ok ? (const void*)src : (const void*)Bh, ok ? 16 : 0);
        }
    };

    float acc[2][2][4];
#pragma unroll
    for (int a = 0; a < 2; a++)
#pragma unroll
        for (int b = 0; b < 2; b++)
#pragma unroll
            for (int r = 0; r < 4; r++) acc[a][b][r] = 0.f;

    const uint32_t arow = (uint32_t)((wm * 32 + (lane & 15)) * 128 + (lane >> 4) * 16);
    const uint32_t brow = (uint32_t)((wn * 16 + (lane & 15)) * 128 + (lane >> 4) * 16);

    fill(0); CP_COMMIT();
    if (nch > 1) fill(1);
    CP_COMMIT();

    for (int c = 0; c < nch; c++) {
        CP_WAIT1();
        __syncthreads();
        if (c + 2 < nch) fill(c + 2);
        CP_COMMIT();

        const uint32_t st = sbase + (c % 3) * STAGE;
#pragma unroll
        for (int ks = 0; ks < 4; ks++) {
            uint32_t bh_[4], bl_[4], ah_[2][4], al_[2][4];
            ldsm4(bh_, st + 2 * A_HALF + SWZ(brow + ks * 32));
            ldsm4(bl_, st + 2 * A_HALF + B_HALF + SWZ(brow + ks * 32));
#pragma unroll
            for (int mt = 0; mt < 2; mt++) {
                ldsm4(ah_[mt], st + SWZ(arow + mt * 2048 + ks * 32));
                ldsm4(al_[mt], st + A_HALF + SWZ(arow + mt * 2048 + ks * 32));
            }
#pragma unroll
            for (int mt = 0; mt < 2; mt++) {
                mma2(acc[mt][0], ah_[mt][0], ah_[mt][1], ah_[mt][2], ah_[mt][3], bh_[0], bh_[2]);
                mma2(acc[mt][1], ah_[mt][0], ah_[mt][1], ah_[mt][2], ah_[mt][3], bh_[1], bh_[3]);
            }
#pragma unroll
            for (int mt = 0; mt < 2; mt++) {
                mma2(acc[mt][0], ah_[mt][0], ah_[mt][1], ah_[mt][2], ah_[mt][3], bl_[0], bl_[2]);
                mma2(acc[mt][1], ah_[mt][0], ah_[mt][1], ah_[mt][2], ah_[mt][3], bl_[1], bl_[3]);
            }
#pragma unroll
            for (int mt = 0; mt < 2; mt++) {
                mma2(acc[mt][0], al_[mt][0], al_[mt][1], al_[mt][2], al_[mt][3], bh_[0], bh_[2]);
                mma2(acc[mt][1], al_[mt][0], al_[mt][1], al_[mt][2], al_[mt][3], bh_[1], bh_[3]);
            }
        }
    }

    const int rbase = i0 + wm * 32 + (lane >> 2);
    const int cb = j0 + wn * 16 + (lane & 3) * 2;
#pragma unroll
    for (int mt = 0; mt < 2; mt++) {
#pragma unroll
        for (int nt = 0; nt < 2; nt++) {
#pragma unroll
            for (int rr = 0; rr < 2; rr++) {
#pragma unroll
                for (int cc = 0; cc < 2; cc++) {
                    int i = rbase + mt * 16 + rr * 8;
                    int j = cb + nt * 8 + cc;
                    if (i >= Md || j >= Nd) continue;
                    float v = acc[mt][nt][rr * 2 + cc];
                    long rm = (long)i * Nd + j;
                    float out;
                    switch (epi) {
                        default:
                        case 0: out = v; break;
                        case 1: out = fmaxf(v + e0[j], 0.f); break;
                        case 2: out = tanhf(v + e0[j]) * e1[j & 7]; break;
                        case 3: out = v + e0[j]; break;
                        case 4: out = fminf(v, e0[rm]); break;
                        case 6: out = 2.f * v; break;
                        case 7: out = (i == j) ? v + 2.f : v; break;
                        case 9: out = v + e0[rm]; break;
                    }
                    if (Cf) Cf[(long)i * Crs + (long)j * Ccs] = out;
                    if (Ch) {
                        bf h16 = __float2bfloat16(out);
                        Ch[rm] = h16;
                        Cl[rm] = __float2bfloat16(out - __bfloat162float(h16));
                    }
                }
            }
        }
    }
    CP_WAIT0();
}

// ---------------- persistent ADMM: BM=64, BN=32, 128 thr, 400 CTAs (1 tile each) ----------------
#define AD_TN 25
#define AD_BLK 400
#define AD_AH (64 * 128)
#define AD_BH (32 * 128)
#define AD_STG (2 * AD_AH + 2 * AD_BH)
#define AD_SMEM (3 * AD_STG)
#define NCH_ADMM 13

__global__ __launch_bounds__(128, 3) void admm_persist(
    const bf* __restrict__ Gh, const bf* __restrict__ Gl,
    const float* __restrict__ Cf, const float* __restrict__ bfv,
    float* __restrict__ yf,
    bf* __restrict__ wah, bf* __restrict__ wal,
    bf* __restrict__ wbh, bf* __restrict__ wbl)
{
    extern __shared__ char sm[];
    const uint32_t sbase = smem_u32(sm);
    const int tid = threadIdx.x;
    const int wid = tid >> 5, lane = tid & 31;
    const int wm = wid >> 1, wn = wid & 1;

    const int i0 = (blockIdx.x / AD_TN) * 64;
    const int j0 = (blockIdx.x % AD_TN) * 32;

    const uint32_t arow = (uint32_t)((wm * 32 + (lane & 15)) * 128 + (lane >> 4) * 16);
    const uint32_t brow = (uint32_t)((wn * 16 + (lane & 15)) * 128 + (lane >> 4) * 16);
    const int rbase = i0 + wm * 32 + (lane >> 2);
    const int cb = j0 + wn * 16 + (lane & 3) * 2;

    for (int t = 0; t < ADMM_ITERS; t++) {
        const bf* Ah = (t & 1) ? wbh : wah;
        const bf* Al = (t & 1) ? wbl : wal;
        bf* Oh = (t & 1) ? wah : wbh;
        bf* Ol = (t & 1) ? wal : wbl;

        auto fill = [&](int c) {
            const uint32_t st = sbase + (c % 3) * AD_STG;
            const int k0 = c << 6;
#pragma unroll
            for (int it = 0; it < 8; it++) {
                int idx = tid + it * 128;
                int seg = idx & 7, r = (idx >> 3) & 63;
                int mat = idx >> 9;
                int gi = i0 + r, gk = k0 + seg * 8;
                bool ok = gk < NC;
                const bf* src = (mat ? Al : Ah) + (long)gi * NC + gk;
                cp16(st + mat * AD_AH + SWZ((uint32_t)(r * 128 + seg * 16)),
                     ok ? (const void*)src : (const void*)Ah, ok ? 16 : 0);
            }
#pragma unroll
            for (int it = 0; it < 4; it++) {
                int idx = tid + it * 128;
                int seg = idx & 7, r = (idx >> 3) & 31;
                int mat = idx >> 8;
                int gj = j0 + r, gk = k0 + seg * 8;
                bool ok = gk < NC;
                const bf* src = (mat ? Gl : Gh) + (long)gj * NC + gk;
                cp16(st + 2 * AD_AH + mat * AD_BH + SWZ((uint32_t)(r * 128 + seg * 16)),
                     ok ? (const void*)src : (const void*)Gh, ok ? 16 : 0);
            }
        };

        float acc[2][2][4];
#pragma unroll
        for (int a = 0; a < 2; a++)
#pragma unroll
            for (int b = 0; b < 2; b++)
#pragma unroll
                for (int r = 0; r < 4; r++) acc[a][b][r] = 0.f;

        fill(0); CP_COMMIT();
        fill(1); CP_COMMIT();

        uint32_t ah_[2][2][4], al_[2][2][4], bh_[2][4], bl_[2][4];

        for (int c = 0; c < NCH_ADMM; c++) {
            CP_WAIT1();
            __syncthreads();
            if (c + 2 < NCH_ADMM) fill(c + 2);
            CP_COMMIT();

            const uint32_t st = sbase + (c % 3) * AD_STG;
            ldsm4(bh_[0], st + 2 * AD_AH + SWZ(brow));
            ldsm4(bl_[0], st + 2 * AD_AH + AD_BH + SWZ(brow));
#pragma unroll
            for (int mt = 0; mt < 2; mt++) {
                ldsm4(ah_[0][mt], st + SWZ(arow + mt * 2048));
                ldsm4(al_[0][mt], st + AD_AH + SWZ(arow + mt * 2048));
            }
#pragma unroll
            for (int ks = 0; ks < 4; ks++) {
                const int cur = ks & 1, nxt = cur ^ 1;
                if (ks < 3) {
                    ldsm4(bh_[nxt], st + 2 * AD_AH + SWZ(brow + (ks + 1) * 32));
                    ldsm4(bl_[nxt], st + 2 * AD_AH + AD_BH + SWZ(brow + (ks + 1) * 32));
#pragma unroll
                    for (int mt = 0; mt < 2; mt++) {
                        ldsm4(ah_[nxt][mt], st + SWZ(arow + mt * 2048 + (ks + 1) * 32));
                        ldsm4(al_[nxt][mt], st + AD_AH + SWZ(arow + mt * 2048 + (ks + 1) * 32));
                    }
                }
#pragma unroll
                for (int mt = 0; mt < 2; mt++) {
                    mma2(acc[mt][0], ah_[cur][mt][0], ah_[cur][mt][1], ah_[cur][mt][2],
                         ah_[cur][mt][3], bh_[cur][0], bh_[cur][2]);
                    mma2(acc[mt][1], ah_[cur][mt][0], ah_[cur][mt][1], ah_[cur][mt][2],
                         ah_[cur][mt][3], bh_[cur][1], bh_[cur][3]);
                }
#pragma unroll
                for (int mt = 0; mt < 2; mt++) {
                    mma2(acc[mt][0], ah_[cur][mt][0], ah_[cur][mt][1], ah_[cur][mt][2],
                         ah_[cur][mt][3], bl_[cur][0], bl_[cur][2]);
                    mma2(acc[mt][1], ah_[cur][mt][0], ah_[cur][mt][1], ah_[cur][mt][2],
                         ah_[cur][mt][3], bl_[cur][1], bl_[cur][3]);
                }
#pragma unroll
                for (int mt = 0; mt < 2; mt++) {
                    mma2(acc[mt][0], al_[cur][mt][0], al_[cur][mt][1], al_[cur][mt][2],
                         al_[cur][mt][3], bh_[cur][0], bh_[cur][2]);
                    mma2(acc[mt][1], al_[cur][mt][0], al_[cur][mt][1], al_[cur][mt][2],
                         al_[cur][mt][3], bh_[cur][1], bh_[cur][3]);
                }
            }
        }
        CP_WAIT0();

#pragma unroll
        for (int mt = 0; mt < 2; mt++) {
#pragma unroll
            for (int nt = 0; nt < 2; nt++) {
#pragma unroll
                for (int rr = 0; rr < 2; rr++) {
                    int i = rbase + mt * 16 + rr * 8;
                    int j = cb + nt * 8;
                    long rm = (long)i * NC + j;
                    float2 cf = *(const float2*)&Cf[rm];
                    float2 yv = *(const float2*)&yf[rm];
                    float2 bv = *(const float2*)&bfv[rm];
                    float s0 = acc[mt][nt][rr * 2 + 0] + cf.x + yv.x;
                    float s1 = acc[mt][nt][rr * 2 + 1] + cf.y + yv.y;
                    float yn0 = fmaxf(s0 - bv.x, 0.f);
                    float yn1 = fmaxf(s1 - bv.y, 0.f);
                    float o0 = s0 - 2.f * yn0;
                    float o1v = s1 - 2.f * yn1;
                    *(float2*)&yf[rm] = make_float2(yn0, yn1);
                    bf h0 = __float2bfloat16(o0);
                    bf h1 = __float2bfloat16(o1v);
                    bf l0 = __float2bfloat16(o0 - __bfloat162float(h0));
                    bf l1 = __float2bfloat16(o1v - __bfloat162float(h1));
                    uint32_t ph = ((uint32_t)*(uint16_t*)&h1 << 16) | *(uint16_t*)&h0;
                    uint32_t pl = ((uint32_t)*(uint16_t*)&l1 << 16) | *(uint16_t*)&l0;
                    *(uint32_t*)&Oh[rm] = ph;
                    *(uint32_t*)&Ol[rm] = pl;
                }
            }
        }
        if (t + 1 < ADMM_ITERS) gbar(&g_cnt1, &g_gen1, AD_BLK, (unsigned)(t + 1));
    }
}

// ---------------- persistent Newton-Schulz: 32x32 tiles, 169 CTAs ----------------
#define NW_BLK 169
#define NW_AH (32 * 128)
#define NW_STG (4 * NW_AH)
#define NW_SMEM (3 * NW_STG)

__global__ __launch_bounds__(128, 4) void newton_persist(
    const bf* __restrict__ Kh, const bf* __restrict__ Kl,
    float* __restrict__ Xaf, float* __restrict__ Xbf,
    bf* __restrict__ Xah, bf* __restrict__ Xal,
    bf* __restrict__ Xbh, bf* __restrict__ Xbl,
    bf* __restrict__ Yh, bf* __restrict__ Yl)
{
    extern __shared__ char sm[];
    const uint32_t sbase = smem_u32(sm);
    const int tid = threadIdx.x;
    const int wid = tid >> 5, lane = tid & 31;
    const int wm = wid >> 1, wn = wid & 1;
    const int i0 = (blockIdx.x / 13) * 32;
    const int j0 = (blockIdx.x % 13) * 32;

    const uint32_t arow = (uint32_t)((wm * 16 + (lane & 15)) * 128 + (lane >> 4) * 16);
    const uint32_t brow = (uint32_t)((wn * 16 + (lane & 15)) * 128 + (lane >> 4) * 16);
    const int rb0 = i0 + wm * 16 + (lane >> 2);
    const int cb0 = j0 + wn * 16 + (lane & 3) * 2;

    unsigned bt = 0;

    auto run_gemm = [&](const bf* Ah, const bf* Al, const bf* Bh, const bf* Bl,
                        int mode, const float* Xcf, float* Xnf, bf* Oh, bf* Ol) {
        auto fill = [&](int c) {
            const uint32_t st = sbase + (c % 3) * NW_STG;
            const int k0 = c << 6;
#pragma unroll
            for (int it = 0; it < 4; it++) {
                int idx = tid + it * 128;
                int seg = idx & 7, r = (idx >> 3) & 31;
                int mat = idx >> 8;
                int gi = i0 + r, gk = k0 + seg * 8;
                bool ok = (gi < DD) && (gk < DD);
                const bf* src = (mat ? Al : Ah) + (long)gi * DD + gk;
                cp16(st + mat * NW_AH + SWZ((uint32_t)(r * 128 + seg * 16)),
                     ok ? (const void*)src : (const void*)Ah, ok ? 16 : 0);
            }
#pragma unroll
            for (int it = 0; it < 4; it++) {
                int idx = tid + it * 128;
                int seg = idx & 7, r = (idx >> 3) & 31;
                int mat = idx >> 8;
                int gj = j0 + r, gk = k0 + seg * 8;
                bool ok = (gj < DD) && (gk < DD);
                const bf* src = (mat ? Bl : Bh) + (long)gj * DD + gk;
                cp16(st + 2 * NW_AH + mat * NW_AH + SWZ((uint32_t)(r * 128 + seg * 16)),
                     ok ? (const void*)src : (const void*)Bh, ok ? 16 : 0);
            }
        };

        float acc[2][4];
#pragma unroll
        for (int b = 0; b < 2; b++)
#pragma unroll
            for (int r = 0; r < 4; r++) acc[b][r] = 0.f;

        const int nch = 7;
        fill(0); CP_COMMIT();
        fill(1); CP_COMMIT();

        for (int c = 0; c < nch; c++) {
            CP_WAIT1();
            __syncthreads();
            if (c + 2 < nch) fill(c + 2);
            CP_COMMIT();

            const uint32_t st = sbase + (c % 3) * NW_STG;
#pragma unroll
            for (int ks = 0; ks < 4; ks++) {
                uint32_t ah_[4], al_[4], bh_[4], bl_[4];
                ldsm4(bh_, st + 2 * NW_AH + SWZ(brow + ks * 32));
                ldsm4(bl_, st + 3 * NW_AH + SWZ(brow + ks * 32));
                ldsm4(ah_, st + SWZ(arow + ks * 32));
                ldsm4(al_, st + NW_AH + SWZ(arow + ks * 32));
                mma2(acc[0], ah_[0], ah_[1], ah_[2], ah_[3], bh_[0], bh_[2]);
                mma2(acc[1], ah_[0], ah_[1], ah_[2], ah_[3], bh_[1], bh_[3]);
                mma2(acc[0], ah_[0], ah_[1], ah_[2], ah_[3], bl_[0], bl_[2]);
                mma2(acc[1], ah_[0], ah_[1], ah_[2], ah_[3], bl_[1], bl_[3]);
                mma2(acc[0], al_[0], al_[1], al_[2], al_[3], bh_[0], bh_[2]);
                mma2(acc[1], al_[0], al_[1], al_[2], al_[3], bh_[1], bh_[3]);
            }
        }
        CP_WAIT0();

#pragma unroll
        for (int nt = 0; nt < 2; nt++) {
#pragma unroll
            for (int rr = 0; rr < 2; rr++) {
                int i = rb0 + rr * 8;
                int j = cb0 + nt * 8;
                if (i >= DD || j >= DD) continue;
                long rm = (long)i * DD + j;
                float v0 = acc[nt][rr * 2 + 0];
                float v1 = acc[nt][rr * 2 + 1];
                float o0, o1v;
                if (mode == 0) { o0 = v0; o1v = v1; }
                else {
                    float2 xc = *(const float2*)&Xcf[rm];
                    o0 = 2.f * xc.x - v0;
                    o1v = 2.f * xc.y - v1;
                    *(float2*)&Xnf[rm] = make_float2(o0, o1v);
                }
                bf h0 = __float2bfloat16(o0);
                bf h1 = __float2bfloat16(o1v);
                bf l0 = __float2bfloat16(o0 - __bfloat162float(h0));
                bf l1 = __float2bfloat16(o1v - __bfloat162float(h1));
                uint32_t ph = ((uint32_t)*(uint16_t*)&h1 << 16) | *(uint16_t*)&h0;
                uint32_t pl = ((uint32_t)*(uint16_t*)&l1 << 16) | *(uint16_t*)&l0;
                *(uint32_t*)&Oh[rm] = ph;
                *(uint32_t*)&Ol[rm] = pl;
            }
        }
    };

    for (int it = 0; it < NEWTON_ITERS; it++) {
        const bf* Ach = (it & 1) ? Xbh : Xah;
        const bf* Acl = (it & 1) ? Xbl : Xal;
        const float* Xcf = (it & 1) ? Xbf : Xaf;
        float* Xnf = (it & 1) ? Xaf : Xbf;
        bf* Xnh = (it & 1) ? Xah : Xbh;
        bf* Xnl = (it & 1) ? Xal : Xbl;

        run_gemm(Ach, Acl, Kh, Kl, 0, nullptr, nullptr, Yh, Yl);
        gbar(&g_cnt2, &g_gen2, NW_BLK, ++bt);
        run_gemm(Yh, Yl, Ach, Acl, 1, Xcf, Xnf, Xnh, Xnl);
        if (it + 1 < NEWTON_ITERS) gbar(&g_cnt2, &g_gen2, NW_BLK, ++bt);
    }
}

// ---------------- prep / small kernels ----------------
__device__ __forceinline__ void split_one(float x, bf* h, bf* l, long o) {
    bf b = __float2bfloat16(x);
    h[o] = b;
    l[o] = __float2bfloat16(x - __bfloat162float(b));
}
__global__ void prep_all(const float* __restrict__ X0, const float* __restrict__ W1,
                         const float* __restrict__ W2, const float* __restrict__ W3,
                         const float* __restrict__ H0, const float* __restrict__ F,
                         bf* x0th, bf* x0tl, bf* w1th, bf* w1tl, bf* w2th, bf* w2tl,
                         bf* w3th, bf* w3tl, bf* h0h, bf* h0l, bf* fh, bf* fl,
                         bf* fth, bf* ftl, float* yzero)
{
    long idx = (long)blockIdx.x * blockDim.x + threadIdx.x;
    const long n0 = NN * NB, n1 = NN * HIDD, n2 = HIDD * HIDD, n3 = HIDD * DD;
    const long n4 = NC * NN, n5 = (long)NC * DD, n6 = (long)NC * DD;
    const long n7 = (long)NB * NC;
    if (idx < n0) {
        int r = idx / NB, c = idx - (long)r * NB;
        split_one(X0[idx], x0th, x0tl, (long)c * NN + r);
        return;
    }
    idx -= n0;
    if (idx < n1) {
        int r = idx / HIDD, c = idx - (long)r * HIDD;
        split_one(W1[idx], w1th, w1tl, (long)c * NN + r);
        return;
    }
    idx -= n1;
    if (idx < n2) {
        int r = idx / HIDD, c = idx - (long)r * HIDD;
        split_one(W2[idx], w2th, w2tl, (long)c * HIDD + r);
        return;
    }
    idx -= n2;
    if (idx < n3) {
        int r = idx / DD, c = idx - (long)r * DD;
        split_one(W3[idx], w3th, w3tl, (long)c * HIDD + r);
        return;
    }
    idx -= n3;
    if (idx < n4) { split_one(H0[idx], h0h, h0l, idx); return; }
    idx -= n4;
    if (idx < n5) { split_one(F[idx], fh, fl, idx); return; }
    idx -= n5;
    if (idx < n6) {
        int r = idx / DD, c = idx - (long)r * DD;
        split_one(F[idx], fth, ftl, (long)c * NC + r);
        return;
    }
    idx -= n6;
    if (idx < n7) { yzero[idx] = 0.f; return; }
}
__global__ void init_sync() { g_cnt1 = 0u; g_gen1 = 0u; g_cnt2 = 0u; g_gen2 = 0u; }
__global__ void transpose_split(const float* __restrict__ s, bf* __restrict__ h,
                                bf* __restrict__ l, int R, int C) {
    long i = (long)blockIdx.x * blockDim.x + threadIdx.x;
    if (i < (long)R * C) {
        int r = i / C, c = i - (long)r * C;
        split_one(s[i], h, l, (long)c * R + r);
    }
}
__global__ void gershgorin_kernel(const float* __restrict__ K, int n) {
    __shared__ float red[512];
    float mx = 0.f;
    for (int i = threadIdx.x; i < n; i += blockDim.x) {
        float sum = 0.f;
        for (int j = 0; j < n; j++) sum += fabsf(K[i * n + j]);
        mx = fmaxf(mx, sum);
    }
    red[threadIdx.x] = mx;
    __syncthreads();
    for (int s = 256; s > 0; s >>= 1) {
        if (threadIdx.x < s) red[threadIdx.x] = fmaxf(red[threadIdx.x], red[threadIdx.x + s]);
        __syncthreads();
    }
    if (threadIdx.x == 0) g_alpha = 2.f / (2.f + red[0]);
}
__global__ void init_diag_split(float* __restrict__ Xf, bf* __restrict__ Xh,
                                bf* __restrict__ Xl, int n) {
    int idx = blockIdx.x * blockDim.x + threadIdx.x;
    if (idx < n * n) {
        int i = idx / n, j = idx - i * n;
        float v = (i == j) ? g_alpha : 0.f;
        Xf[idx] = v;
        bf b = __float2bfloat16(v);
        Xh[idx] = b;
        Xl[idx] = __float2bfloat16(v - __bfloat162float(b));
    }
}

// ---------------- host ----------------
static inline void tg(const bf* Ah, const bf* Al, const bf* Bh, const bf* Bl,
                      float* Cf, bf* Ch, bf* Cl, long Crs, long Ccs,
                      int M, int N, int K, int epi,
                      const float* e0 = nullptr, const float* e1 = nullptr,
                      const float* e2 = nullptr, float* o1 = nullptr)
{
    dim3 grid((N + 63) / 64, (M + 63) / 64);
    tgemm<<<grid, 256, SMEMB>>>(Ah, Al, Bh, Bl, Cf, Ch, Cl, Crs, Ccs,
                                M, N, K, epi, e0, e1, e2, o1);
}

template <typename T> static inline T* sym(const void* s) {
    void* p = nullptr;
    cudaGetSymbolAddress(&p, s);
    return (T*)p;
}

extern "C" void kernel_launch(void* const* d_in, const int* in_sizes, int n_in,
                              void* d_out, int out_size)
{
    const float* X0   = (const float*)d_in[0];
    const float* W1   = (const float*)d_in[1];
    const float* b1   = (const float*)d_in[2];
    const float* W2   = (const float*)d_in[3];
    const float* b2   = (const float*)d_in[4];
    const float* W3   = (const float*)d_in[5];
    const float* b3   = (const float*)d_in[6];
    const float* ubar = (const float*)d_in[7];
    const float* F    = (const float*)d_in[8];
    const float* gg   = (const float*)d_in[9];
    const float* H0   = (const float*)d_in[10];
    float* out = (float*)d_out;

    cudaFuncSetAttribute(tgemm, cudaFuncAttributeMaxDynamicSharedMemorySize, SMEMB);
    cudaFuncSetAttribute(admm_persist, cudaFuncAttributeMaxDynamicSharedMemorySize, AD_SMEM);
    cudaFuncSetAttribute(newton_persist, cudaFuncAttributeMaxDynamicSharedMemorySize, NW_SMEM);

    float *pKf = sym<float>(dKf), *pXaf = sym<float>(dXaf), *pXbf = sym<float>(dXbf);
    float *pFKf = sym<float>(dFKf), *pCf = sym<float>(dCf_), *pbf = sym<float>(dbf_);
    float *pyf = sym<float>(dyf_), *pUf = sym<float>(dUf_);

    bf *x0th = sym<bf>(X0Th), *x0tl = sym<bf>(X0Tl);
    bf *w1th = sym<bf>(W1Th), *w1tl = sym<bf>(W1Tl);
    bf *w2th = sym<bf>(W2Th), *w2tl = sym<bf>(W2Tl);
    bf *w3th = sym<bf>(W3Th), *w3tl = sym<bf>(W3Tl);
    bf *h0h = sym<bf>(H0h_), *h0l = sym<bf>(H0l_);
    bf *fh = sym<bf>(Fh_), *fl = sym<bf>(Fl_);
    bf *fth = sym<bf>(FTh_), *ftl = sym<bf>(FTl_);
    bf *h1h = sym<bf>(H1h_), *h1l = sym<bf>(H1l_);
    bf *h2h = sym<bf>(H2h_), *h2l = sym<bf>(H2l_);
    bf *vh = sym<bf>(Vh_), *vl = sym<bf>(Vl_);
    bf *kh = sym<bf>(Kh_), *kl = sym<bf>(Kl_);
    bf *xah = sym<bf>(Xah_), *xal = sym<bf>(Xal_);
    bf *xbh = sym<bf>(Xbh_), *xbl = sym<bf>(Xbl_);
    bf *yh = sym<bf>(Yh_), *yl = sym<bf>(Yl_);
    bf *fkh = sym<bf>(FKh_), *fkl = sym<bf>(FKl_);
    bf *fkth = sym<bf>(FKTh_), *fktl = sym<bf>(FKTl_);
    bf *ghh = sym<bf>(Gh_), *gll = sym<bf>(Gl_);
    bf *wah = sym<bf>(Wah_), *wal = sym<bf>(Wal_);
    bf *wbh = sym<bf>(Wbh_), *wbl = sym<bf>(Wbl_);

    // fused prep (+ y zero) + sync counters
    {
        long total = (long)NN*NB + (long)NN*HIDD + (long)HIDD*HIDD + (long)HIDD*DD
                   + (long)NC*NN + (long)NC*DD + (long)NC*DD + (long)NB*NC;
        prep_all<<<(int)((total + 255) / 256), 256>>>(
            X0, W1, W2, W3, H0, F,
            x0th, x0tl, w1th, w1tl, w2th, w2tl, w3th, w3tl,
            h0h, h0l, fh, fl, fth, ftl, pyf);
    }
    init_sync<<<1, 1>>>();

    // MLP head
    tg(x0th, x0tl, w1th, w1tl, nullptr, h1h, h1l, HIDD, 1, NB, HIDD, NN, 1, b1);
    tg(h1h, h1l, w2th, w2tl, nullptr, h2h, h2l, HIDD, 1, NB, HIDD, HIDD, 1, b2);
    tg(h2h, h2l, w3th, w3tl, nullptr, vh, vl, DD, 1, NB, DD, HIDD, 2, b3, ubar);

    // b = g + X0^T H0^T
    tg(x0th, x0tl, h0h, h0l, pbf, nullptr, nullptr, NC, 1, NB, NC, NN, 3, gg);

    // K = 2I + F^T F
    tg(fth, ftl, fth, ftl, pKf, kh, kl, DD, 1, DD, DD, NC, 7);

    // Kinv: persistent Newton-Schulz (8 iters -> result in xa)
    gershgorin_kernel<<<1, 512>>>(pKf, DD);
    init_diag_split<<<(DD*DD + 255)/256, 256>>>(pXaf, xah, xal, DD);
    newton_persist<<<NW_BLK, 128, NW_SMEM>>>(kh, kl, pXaf, pXbf,
                                             xah, xal, xbh, xbl, yh, yl);

    // precompute: FK, FKT, G, C
    tg(fh, fl, xah, xal, pFKf, fkh, fkl, DD, 1, NC, DD, DD, 0);
    transpose_split<<<(NC*DD + 255)/256, 256>>>(pFKf, fkth, fktl, NC, DD);
    tg(fkh, fkl, fh, fl, nullptr, ghh, gll, NC, 1, NC, NC, DD, 0);
    tg(vh, vl, fkh, fkl, pCf, nullptr, nullptr, NC, 1, NB, NC, DD, 6);

    // init: w0 = min(V F^T, b)
    tg(vh, vl, fh, fl, nullptr, wah, wal, NC, 1, NB, NC, DD, 4, pbf);

    // ADMM: persistent, 40 iters, one 64x32 tile per CTA (400 CTAs, all resident)
    admm_persist<<<AD_BLK, 128, AD_SMEM>>>(ghh, gll, pCf, pbf, pyf,
                                           wah, wal, wbh, wbl);
    // even iters -> final w in wah/wal

    // u = 2 V Kinv + w FK ; out = u^T
    tg(vh, vl, xah, xal, pUf, nullptr, nullptr, DD, 1, NB, DD, DD, 6);
    tg(wah, wal, fkth, fktl, out, nullptr, nullptr, 1, NB, NB, DD, NC, 9, pUf);
}